// round 1
// baseline (speedup 1.0000x reference)
#include <cuda_runtime.h>

// ---------------- problem constants (from reference setup_inputs) ----------
#define BN   2
#define HN   16
#define BH   32          // B*H
#define LN   2048
#define DN   64
#define FN   64
#define PHI  128         // 2F
#define CK   128         // chunk length
#define NC   16          // LN/CK
#define EPSF 1e-12f

#define PLD  132         // padded leading dim for [*, 128] phi tiles (float4-aligned, conflict-light)
#define VLD  68          // padded leading dim for [*, 64] tiles

// ---------------- scratch (static device globals; no allocation) -----------
__device__ float g_phiq[(size_t)BH*LN*PHI];      // 33.5 MB
__device__ float g_phik[(size_t)BH*LN*PHI];      // 33.5 MB
__device__ float g_state[(size_t)BH*NC*PHI*DN];  // 16.8 MB  per-chunk K^T V
__device__ float g_zst  [(size_t)BH*NC*PHI];     //          per-chunk sum(phi_k)
__device__ float g_spref[(size_t)BH*NC*PHI*DN];  // exclusive prefixes
__device__ float g_zpref[(size_t)BH*NC*PHI];

#define DOT4(acc, a4, b4) { (acc) += (a4).x*(b4).x + (a4).y*(b4).y + (a4).z*(b4).z + (a4).w*(b4).w; }
#define OP4(yrow, a, b4)  { (yrow)[0] += (a)*(b4).x; (yrow)[1] += (a)*(b4).y; (yrow)[2] += (a)*(b4).z; (yrow)[3] += (a)*(b4).w; }

// ============================================================================
// Pass 1: hedgehog feature map.  phi = clip([softmax(xW), softmax(-xW)], eps)
// grid (LN/8, BH), block 256 (8 warps, one row per warp). which: 0->phiq, 1->phik
// ============================================================================
__global__ __launch_bounds__(256) void fmap_kernel(
    const float* __restrict__ x, const float* __restrict__ W,
    const int* __restrict__ lidx, int which)
{
    __shared__ float sW[DN*FN];     // 16 KB
    __shared__ float sx[8][DN];     // 2 KB
    const int bh  = blockIdx.y;
    const int h   = bh % HN;
    const int tid = threadIdx.x;
    const int li  = lidx[0];

    const float* Wh = W + ((size_t)li*HN + h)*DN*FN;
    for (int i = tid; i < DN*FN; i += 256) sW[i] = Wh[i];

    const int w    = tid >> 5;
    const int lane = tid & 31;
    const int row  = blockIdx.x*8 + w;
    const float* xr = x + ((size_t)bh*LN + row)*DN;
    sx[w][lane]      = xr[lane];
    sx[w][lane + 32] = xr[lane + 32];
    __syncthreads();

    float o0 = 0.f, o1 = 0.f;
    #pragma unroll
    for (int d = 0; d < DN; d++) {
        float xv = sx[w][d];
        o0 += xv * sW[d*FN + lane];
        o1 += xv * sW[d*FN + lane + 32];
    }

    float mx = fmaxf(o0, o1), mn = fminf(o0, o1);
    #pragma unroll
    for (int off = 16; off; off >>= 1) {
        mx = fmaxf(mx, __shfl_xor_sync(0xffffffffu, mx, off));
        mn = fminf(mn, __shfl_xor_sync(0xffffffffu, mn, off));
    }
    float e0 = expf(o0 - mx), e1 = expf(o1 - mx);   // softmax(o)
    float n0 = expf(mn - o0), n1 = expf(mn - o1);   // softmax(-o): max(-o) = -min(o)
    float se = e0 + e1, sn = n0 + n1;
    #pragma unroll
    for (int off = 16; off; off >>= 1) {
        se += __shfl_xor_sync(0xffffffffu, se, off);
        sn += __shfl_xor_sync(0xffffffffu, sn, off);
    }
    float ie = 1.f/se, in_ = 1.f/sn;

    float* pr = (which ? g_phik : g_phiq) + ((size_t)bh*LN + row)*PHI;
    pr[lane]        = fmaxf(e0*ie,  EPSF);
    pr[lane + 32]   = fmaxf(e1*ie,  EPSF);
    pr[64 + lane]   = fmaxf(n0*in_, EPSF);
    pr[96 + lane]   = fmaxf(n1*in_, EPSF);
}

// ============================================================================
// Pass 2: per-chunk states  S_c[f][d] = sum_n phi_k[n][f] v[n][d],  z_c[f]
// grid (NC, BH), block 256, dynamic smem 100 KB
// ============================================================================
__global__ __launch_bounds__(256) void state_kernel(const float* __restrict__ v)
{
    extern __shared__ float sm[];
    float* sPhi = sm;               // CK*PLD
    float* sV   = sm + CK*PLD;      // CK*VLD
    const int c = blockIdx.x, bh = blockIdx.y, tid = threadIdx.x;
    const size_t tok0 = (size_t)bh*LN + (size_t)c*CK;

    const float* pk = g_phik + tok0*PHI;
    for (int i = tid; i < CK*PHI; i += 256) sPhi[(i>>7)*PLD + (i&127)] = pk[i];
    const float* vr = v + tok0*DN;
    for (int i = tid; i < CK*DN;  i += 256) sV[(i>>6)*VLD + (i&63)]   = vr[i];
    __syncthreads();

    const int f0 = (tid >> 4) * 8, d0 = (tid & 15) * 4;
    float acc[8][4];
    #pragma unroll
    for (int i = 0; i < 8; i++)
        #pragma unroll
        for (int j = 0; j < 4; j++) acc[i][j] = 0.f;

    for (int n = 0; n < CK; n++) {
        float4 a0 = *(const float4*)&sPhi[n*PLD + f0];
        float4 a1 = *(const float4*)&sPhi[n*PLD + f0 + 4];
        float4 vv = *(const float4*)&sV[n*VLD + d0];
        OP4(acc[0], a0.x, vv); OP4(acc[1], a0.y, vv); OP4(acc[2], a0.z, vv); OP4(acc[3], a0.w, vv);
        OP4(acc[4], a1.x, vv); OP4(acc[5], a1.y, vv); OP4(acc[6], a1.z, vv); OP4(acc[7], a1.w, vv);
    }

    float* So = g_state + ((size_t)bh*NC + c)*(PHI*DN);
    #pragma unroll
    for (int i = 0; i < 8; i++)
        #pragma unroll
        for (int j = 0; j < 4; j++)
            So[(f0+i)*DN + d0 + j] = acc[i][j];

    if (tid < PHI) {
        float z = 0.f;
        for (int n = 0; n < CK; n++) z += sPhi[n*PLD + tid];
        g_zst[((size_t)bh*NC + c)*PHI + tid] = z;
    }
}

// ============================================================================
// Pass 2b: exclusive prefix over chunks.  grid BH, block 256.
// ============================================================================
__global__ __launch_bounds__(256) void prefix_kernel()
{
    const int bh = blockIdx.x, tid = threadIdx.x;
    float run[32];
    #pragma unroll
    for (int k = 0; k < 32; k++) run[k] = 0.f;
    const size_t base = (size_t)bh*NC*PHI*DN;
    for (int c = 0; c < NC; c++) {
        const size_t off = base + (size_t)c*PHI*DN;
        #pragma unroll
        for (int k = 0; k < 32; k++) {
            g_spref[off + tid + k*256] = run[k];
            run[k] += g_state[off + tid + k*256];
        }
    }
    if (tid < PHI) {
        float z = 0.f;
        const size_t zb = (size_t)bh*NC*PHI;
        for (int c = 0; c < NC; c++) {
            g_zpref[zb + (size_t)c*PHI + tid] = z;
            z += g_zst[zb + (size_t)c*PHI + tid];
        }
    }
}

// ============================================================================
// Pass 3: per-chunk output.
//   y[m] = phi_q[m] @ S_pref + sum_{n<=m, same chunk} (phi_q[m].phi_k[n]) v[n]
//   den[m] = phi_q[m].z_pref + intra masked row-sum;  out = y / (den + eps)
// grid (NC, BH), block 256, dynamic smem ~185 KB
// ============================================================================
__global__ __launch_bounds__(256) void out_kernel(
    const float* __restrict__ v, float* __restrict__ out)
{
    extern __shared__ float sm[];
    float* sQ   = sm;                    // 128*132
    float* sSp  = sQ  + CK*PLD;          // 128*68
    float* sK   = sSp + PHI*VLD;         // 64*132
    float* sV   = sK  + 64*PLD;          // 64*68
    float* sS   = sV  + 64*VLD;          // 128*68
    float* sZ   = sS  + CK*VLD;          // 128
    float* sDen = sZ  + PHI;             // 128

    const int c = blockIdx.x, bh = blockIdx.y, tid = threadIdx.x;
    const size_t tok0 = (size_t)bh*LN + (size_t)c*CK;

    const float* pq = g_phiq + tok0*PHI;
    for (int i = tid; i < CK*PHI; i += 256) sQ[(i>>7)*PLD + (i&127)] = pq[i];
    const float* sp = g_spref + ((size_t)bh*NC + c)*(PHI*DN);
    for (int i = tid; i < PHI*DN; i += 256) sSp[(i>>6)*VLD + (i&63)] = sp[i];
    if (tid < PHI) sZ[tid] = g_zpref[((size_t)bh*NC + c)*PHI + tid];
    __syncthreads();

    // denominator, inter-chunk part
    if (tid < CK) {
        float ds = 0.f;
        #pragma unroll 8
        for (int f = 0; f < PHI; f++) ds += sQ[tid*PLD + f] * sZ[f];
        sDen[tid] = ds;
    }

    const int ty = tid >> 4, tx = tid & 15;
    const int m0 = ty * 8, d0 = tx * 4;
    float y[8][4];
    #pragma unroll
    for (int i = 0; i < 8; i++)
        #pragma unroll
        for (int j = 0; j < 4; j++) y[i][j] = 0.f;

    // GEMM1: y = phiQ @ S_pref
    for (int f = 0; f < PHI; f += 4) {
        float4 sp0 = *(const float4*)&sSp[(f+0)*VLD + d0];
        float4 sp1 = *(const float4*)&sSp[(f+1)*VLD + d0];
        float4 sp2 = *(const float4*)&sSp[(f+2)*VLD + d0];
        float4 sp3 = *(const float4*)&sSp[(f+3)*VLD + d0];
        #pragma unroll
        for (int i = 0; i < 8; i++) {
            float4 q4 = *(const float4*)&sQ[(m0+i)*PLD + f];
            OP4(y[i], q4.x, sp0); OP4(y[i], q4.y, sp1);
            OP4(y[i], q4.z, sp2); OP4(y[i], q4.w, sp3);
        }
    }

    // intra-chunk: 2 n-tiles of 64
    for (int nt = 0; nt < 2; nt++) {
        __syncthreads();   // protect sK/sV/sS from previous tile's readers
        const size_t tk = tok0 + (size_t)nt*64;
        const float* pk = g_phik + tk*PHI;
        for (int i = tid; i < 64*PHI; i += 256) sK[(i>>7)*PLD + (i&127)] = pk[i];
        const float* vr = v + tk*DN;
        for (int i = tid; i < 64*DN;  i += 256) sV[(i>>6)*VLD + (i&63)]  = vr[i];
        __syncthreads();

        const int n0 = tx * 4;
        const int nbase = nt*64 + n0;
        const bool live = (m0 + 7 >= nt*64);   // any unmasked row in this thread's tile?

        float s[8][4];
        #pragma unroll
        for (int i = 0; i < 8; i++)
            #pragma unroll
            for (int j = 0; j < 4; j++) s[i][j] = 0.f;

        if (live) {
            for (int f = 0; f < PHI; f += 4) {
                float4 k0 = *(const float4*)&sK[(n0+0)*PLD + f];
                float4 k1 = *(const float4*)&sK[(n0+1)*PLD + f];
                float4 k2 = *(const float4*)&sK[(n0+2)*PLD + f];
                float4 k3 = *(const float4*)&sK[(n0+3)*PLD + f];
                #pragma unroll
                for (int i = 0; i < 8; i++) {
                    float4 q4 = *(const float4*)&sQ[(m0+i)*PLD + f];
                    DOT4(s[i][0], q4, k0); DOT4(s[i][1], q4, k1);
                    DOT4(s[i][2], q4, k2); DOT4(s[i][3], q4, k3);
                }
            }
        }
        // causal mask (local indices; same chunk) + stage to smem
        #pragma unroll
        for (int i = 0; i < 8; i++) {
            const int m = m0 + i;
            #pragma unroll
            for (int j = 0; j < 4; j++) {
                float sv_ = (nbase + j <= m) ? s[i][j] : 0.f;
                sS[m*VLD + n0 + j] = sv_;
            }
        }
        __syncthreads();

        // AV: y += sS @ sV ; tx==0 threads also fold denominator row-sums (race-free)
        if (live || tx == 0) {
            float dsum[8];
            #pragma unroll
            for (int i = 0; i < 8; i++) dsum[i] = 0.f;
            for (int n = 0; n < 64; n += 4) {
                float4 v0 = *(const float4*)&sV[(n+0)*VLD + d0];
                float4 v1 = *(const float4*)&sV[(n+1)*VLD + d0];
                float4 v2 = *(const float4*)&sV[(n+2)*VLD + d0];
                float4 v3 = *(const float4*)&sV[(n+3)*VLD + d0];
                #pragma unroll
                for (int i = 0; i < 8; i++) {
                    float4 s4 = *(const float4*)&sS[(m0+i)*VLD + n];
                    OP4(y[i], s4.x, v0); OP4(y[i], s4.y, v1);
                    OP4(y[i], s4.z, v2); OP4(y[i], s4.w, v3);
                    if (tx == 0) dsum[i] += s4.x + s4.y + s4.z + s4.w;
                }
            }
            if (tx == 0) {
                #pragma unroll
                for (int i = 0; i < 8; i++) sDen[m0+i] += dsum[i];
            }
        }
    }
    __syncthreads();

    float* orow = out + tok0*DN;
    #pragma unroll
    for (int i = 0; i < 8; i++) {
        const float inv = 1.f / (sDen[m0+i] + EPSF);
        #pragma unroll
        for (int j = 0; j < 4; j++)
            orow[(size_t)(m0+i)*DN + d0 + j] = y[i][j] * inv;
    }
}

// ============================================================================
extern "C" void kernel_launch(void* const* d_in, const int* in_sizes, int n_in,
                              void* d_out, int out_size)
{
    const float* q  = (const float*)d_in[0];
    const float* k  = (const float*)d_in[1];
    const float* v  = (const float*)d_in[2];
    const float* Wq = (const float*)d_in[3];
    const float* Wk = (const float*)d_in[4];
    const int*   li = (const int*)d_in[5];
    float* out = (float*)d_out;

    const int SMEM_STATE = (CK*PLD + CK*VLD) * 4;                                   // 102400 B
    const int SMEM_OUT   = (CK*PLD + PHI*VLD + 64*PLD + 64*VLD + CK*VLD + PHI + CK) * 4; // 189440 B
    cudaFuncSetAttribute(state_kernel, cudaFuncAttributeMaxDynamicSharedMemorySize, SMEM_STATE);
    cudaFuncSetAttribute(out_kernel,   cudaFuncAttributeMaxDynamicSharedMemorySize, SMEM_OUT);

    dim3 g1(LN/8, BH);
    fmap_kernel<<<g1, 256>>>(q, Wq, li, 0);
    fmap_kernel<<<g1, 256>>>(k, Wk, li, 1);

    dim3 g2(NC, BH);
    state_kernel<<<g2, 256, SMEM_STATE>>>(v);
    prefix_kernel<<<BH, 256>>>();
    out_kernel<<<g2, 256, SMEM_OUT>>>(v, out);
}

// round 3
// speedup vs baseline: 1.3708x; 1.3708x over previous
#include <cuda_runtime.h>

// ---------------- problem constants (from reference setup_inputs) ----------
#define BN   2
#define HN   16
#define BH   32          // B*H
#define LN   2048
#define DN   64
#define FN   64
#define PHI  128         // 2F
#define CK   128         // chunk length
#define NC   16          // LN/CK
#define EPSF 1e-12f

#define PLD  132         // padded leading dim for [*, 128] phi tiles
#define VLD  68          // padded leading dim for [*, 64] tiles

// ---------------- scratch (static device globals; no allocation) -----------
__device__ float g_phiq[(size_t)BH*LN*PHI];      // 33.5 MB
__device__ float g_phik[(size_t)BH*LN*PHI];      // 33.5 MB
__device__ float g_state[(size_t)BH*NC*PHI*DN];  // 16.8 MB  per-chunk K^T V
__device__ float g_zst  [(size_t)BH*NC*PHI];
__device__ float g_spref[(size_t)BH*NC*PHI*DN];
__device__ float g_zpref[(size_t)BH*NC*PHI];

#define DOT4(acc, a4, b4) { (acc) += (a4).x*(b4).x + (a4).y*(b4).y + (a4).z*(b4).z + (a4).w*(b4).w; }
#define OP4(yrow, a, b4)  { (yrow)[0] += (a)*(b4).x; (yrow)[1] += (a)*(b4).y; (yrow)[2] += (a)*(b4).z; (yrow)[3] += (a)*(b4).w; }

// ============================================================================
// Pass 1: hedgehog feature map.  phi = clip([softmax(xW), softmax(-xW)], eps)
// grid (LN/32, BH, 2), block 256 (8 warps). Each warp handles 4 rows:
// W values loaded once per (d, lane) and reused across 4 rows (4x FFMA per LDS).
// z-dim: 0 -> q/Wq -> g_phiq, 1 -> k/Wk -> g_phik
// ============================================================================
__global__ __launch_bounds__(256) void fmap_kernel(
    const float* __restrict__ q, const float* __restrict__ k,
    const float* __restrict__ Wq, const float* __restrict__ Wk,
    const int* __restrict__ lidx)
{
    __shared__ float sW[DN*FN];      // 16 KB
    __shared__ float sx[32][68];     // 32 rows, padded (272B rows, 16B aligned)

    const int which = blockIdx.z;
    const float* x = which ? k  : q;
    const float* W = which ? Wk : Wq;

    const int bh  = blockIdx.y;
    const int h   = bh % HN;
    const int tid = threadIdx.x;
    const int li  = lidx[0];

    const float* Wh = W + ((size_t)li*HN + h)*DN*FN;
    for (int i = tid; i < DN*FN/4; i += 256)
        ((float4*)sW)[i] = ((const float4*)Wh)[i];

    const int row0 = blockIdx.x * 32;
    const float* xr = x + ((size_t)bh*LN + row0)*DN;
    for (int i = tid; i < 32*DN/4; i += 256) {
        const int r = i >> 4, c = i & 15;
        *(float4*)&sx[r][c*4] = ((const float4*)xr)[i];
    }
    __syncthreads();

    const int w    = tid >> 5;
    const int lane = tid & 31;

    float o[4][2];
    #pragma unroll
    for (int r = 0; r < 4; r++) { o[r][0] = 0.f; o[r][1] = 0.f; }

    #pragma unroll 4
    for (int d = 0; d < DN; d++) {
        const float w0 = sW[d*FN + lane];
        const float w1 = sW[d*FN + lane + 32];
        #pragma unroll
        for (int r = 0; r < 4; r++) {
            const float xv = sx[w*4 + r][d];
            o[r][0] += xv * w0;
            o[r][1] += xv * w1;
        }
    }

    float* phidst = which ? g_phik : g_phiq;
    #pragma unroll
    for (int r = 0; r < 4; r++) {
        float o0 = o[r][0], o1 = o[r][1];
        float mx = fmaxf(o0, o1), mn = fminf(o0, o1);
        #pragma unroll
        for (int off = 16; off; off >>= 1) {
            mx = fmaxf(mx, __shfl_xor_sync(0xffffffffu, mx, off));
            mn = fminf(mn, __shfl_xor_sync(0xffffffffu, mn, off));
        }
        float e0 = __expf(o0 - mx), e1 = __expf(o1 - mx);   // softmax(o)
        float n0 = __expf(mn - o0), n1 = __expf(mn - o1);   // softmax(-o)
        float se = e0 + e1, sn = n0 + n1;
        #pragma unroll
        for (int off = 16; off; off >>= 1) {
            se += __shfl_xor_sync(0xffffffffu, se, off);
            sn += __shfl_xor_sync(0xffffffffu, sn, off);
        }
        const float ie = 1.f/se, in_ = 1.f/sn;
        float* pr = phidst + ((size_t)bh*LN + row0 + w*4 + r)*PHI;
        pr[lane]      = fmaxf(e0*ie,  EPSF);
        pr[lane + 32] = fmaxf(e1*ie,  EPSF);
        pr[64 + lane] = fmaxf(n0*in_, EPSF);
        pr[96 + lane] = fmaxf(n1*in_, EPSF);
    }
}

// ============================================================================
// Pass 2: per-chunk states  S_c[f][d] = sum_n phi_k[n][f] v[n][d],  z_c[f]
// grid (NC, BH), block 256, dynamic smem 100 KB (2 CTAs/SM)
// ============================================================================
__global__ __launch_bounds__(256) void state_kernel(const float* __restrict__ v)
{
    extern __shared__ float sm[];
    float* sPhi = sm;               // CK*PLD
    float* sV   = sm + CK*PLD;      // CK*VLD
    const int c = blockIdx.x, bh = blockIdx.y, tid = threadIdx.x;
    const size_t tok0 = (size_t)bh*LN + (size_t)c*CK;

    const float* pk = g_phik + tok0*PHI;
    for (int i = tid; i < CK*PHI; i += 256) sPhi[(i>>7)*PLD + (i&127)] = pk[i];
    const float* vr = v + tok0*DN;
    for (int i = tid; i < CK*DN;  i += 256) sV[(i>>6)*VLD + (i&63)]   = vr[i];
    __syncthreads();

    const int f0 = (tid >> 4) * 8, d0 = (tid & 15) * 4;
    float acc[8][4];
    #pragma unroll
    for (int i = 0; i < 8; i++)
        #pragma unroll
        for (int j = 0; j < 4; j++) acc[i][j] = 0.f;

    for (int n = 0; n < CK; n++) {
        float4 a0 = *(const float4*)&sPhi[n*PLD + f0];
        float4 a1 = *(const float4*)&sPhi[n*PLD + f0 + 4];
        float4 vv = *(const float4*)&sV[n*VLD + d0];
        OP4(acc[0], a0.x, vv); OP4(acc[1], a0.y, vv); OP4(acc[2], a0.z, vv); OP4(acc[3], a0.w, vv);
        OP4(acc[4], a1.x, vv); OP4(acc[5], a1.y, vv); OP4(acc[6], a1.z, vv); OP4(acc[7], a1.w, vv);
    }

    float* So = g_state + ((size_t)bh*NC + c)*(PHI*DN);
    #pragma unroll
    for (int i = 0; i < 8; i++)
        #pragma unroll
        for (int j = 0; j < 4; j++)
            So[(f0+i)*DN + d0 + j] = acc[i][j];

    if (tid < PHI) {
        float z = 0.f;
        for (int n = 0; n < CK; n++) z += sPhi[n*PLD + tid];
        g_zst[((size_t)bh*NC + c)*PHI + tid] = z;
    }
}

// ============================================================================
// Pass 2b: exclusive prefix over chunks — fully parallel.
// Each thread owns one (bh, f, d) chain: 16 independent loads (MLP=16),
// register scan, 16 stores. grid (1024, 2), block 256.
//   y==0: state prefixes (BH*PHI*DN = 262144 chains)
//   y==1: z prefixes     (BH*PHI     =   4096 chains; blocks >=16 idle)
// ============================================================================
__global__ __launch_bounds__(256) void prefix_kernel()
{
    const int t = blockIdx.x * 256 + threadIdx.x;
    if (blockIdx.y == 0) {
        const int bh = t >> 13, idx = t & 8191;
        const size_t base = ((size_t)bh*NC)*(PHI*DN) + idx;
        float vals[NC];
        #pragma unroll
        for (int c = 0; c < NC; c++) vals[c] = g_state[base + (size_t)c*(PHI*DN)];
        float run = 0.f;
        #pragma unroll
        for (int c = 0; c < NC; c++) {
            g_spref[base + (size_t)c*(PHI*DN)] = run;
            run += vals[c];
        }
    } else {
        if (t >= BH*PHI) return;
        const int bh = t >> 7, idx = t & 127;
        const size_t base = ((size_t)bh*NC)*PHI + idx;
        float vals[NC];
        #pragma unroll
        for (int c = 0; c < NC; c++) vals[c] = g_zst[base + (size_t)c*PHI];
        float run = 0.f;
        #pragma unroll
        for (int c = 0; c < NC; c++) {
            g_zpref[base + (size_t)c*PHI] = run;
            run += vals[c];
        }
    }
}

// ============================================================================
// Pass 3: per-chunk output.
//   y[m] = phi_q[m] @ S_pref + sum_{n<=m, same chunk} (phi_q[m].phi_k[n]) v[n]
//   den[m] = phi_q[m].z_pref + intra masked row-sum;  out = y / (den + eps)
// grid (NC, BH), block 256, dynamic smem ~185 KB
// ============================================================================
__global__ __launch_bounds__(256) void out_kernel(
    const float* __restrict__ v, float* __restrict__ out)
{
    extern __shared__ float sm[];
    float* sQ   = sm;                    // 128*132
    float* sSp  = sQ  + CK*PLD;          // 128*68
    float* sK   = sSp + PHI*VLD;         // 64*132
    float* sV   = sK  + 64*PLD;          // 64*68
    float* sS   = sV  + 64*VLD;          // 128*68
    float* sZ   = sS  + CK*VLD;          // 128
    float* sDen = sZ  + PHI;             // 128

    const int c = blockIdx.x, bh = blockIdx.y, tid = threadIdx.x;
    const size_t tok0 = (size_t)bh*LN + (size_t)c*CK;

    const float* pq = g_phiq + tok0*PHI;
    for (int i = tid; i < CK*PHI; i += 256) sQ[(i>>7)*PLD + (i&127)] = pq[i];
    const float* sp = g_spref + ((size_t)bh*NC + c)*(PHI*DN);
    for (int i = tid; i < PHI*DN; i += 256) sSp[(i>>6)*VLD + (i&63)] = sp[i];
    if (tid < PHI) sZ[tid] = g_zpref[((size_t)bh*NC + c)*PHI + tid];
    __syncthreads();

    // denominator, inter-chunk part (vectorized)
    if (tid < CK) {
        float ds = 0.f;
        #pragma unroll 8
        for (int f = 0; f < PHI; f += 4) {
            float4 q4 = *(const float4*)&sQ[tid*PLD + f];
            float4 z4 = *(const float4*)&sZ[f];
            DOT4(ds, q4, z4);
        }
        sDen[tid] = ds;
    }

    const int ty = tid >> 4, tx = tid & 15;
    const int m0 = ty * 8, d0 = tx * 4;
    float y[8][4];
    #pragma unroll
    for (int i = 0; i < 8; i++)
        #pragma unroll
        for (int j = 0; j < 4; j++) y[i][j] = 0.f;

    // GEMM1: y = phiQ @ S_pref
    for (int f = 0; f < PHI; f += 4) {
        float4 sp0 = *(const float4*)&sSp[(f+0)*VLD + d0];
        float4 sp1 = *(const float4*)&sSp[(f+1)*VLD + d0];
        float4 sp2 = *(const float4*)&sSp[(f+2)*VLD + d0];
        float4 sp3 = *(const float4*)&sSp[(f+3)*VLD + d0];
        #pragma unroll
        for (int i = 0; i < 8; i++) {
            float4 q4 = *(const float4*)&sQ[(m0+i)*PLD + f];
            OP4(y[i], q4.x, sp0); OP4(y[i], q4.y, sp1);
            OP4(y[i], q4.z, sp2); OP4(y[i], q4.w, sp3);
        }
    }

    // intra-chunk: 2 n-tiles of 64
    for (int nt = 0; nt < 2; nt++) {
        __syncthreads();
        const size_t tk = tok0 + (size_t)nt*64;
        const float* pk = g_phik + tk*PHI;
        for (int i = tid; i < 64*PHI; i += 256) sK[(i>>7)*PLD + (i&127)] = pk[i];
        const float* vr = v + tk*DN;
        for (int i = tid; i < 64*DN;  i += 256) sV[(i>>6)*VLD + (i&63)]  = vr[i];
        __syncthreads();

        const int n0 = tx * 4;
        const int nbase = nt*64 + n0;
        const bool live = (m0 + 7 >= nt*64);

        float s[8][4];
        #pragma unroll
        for (int i = 0; i < 8; i++)
            #pragma unroll
            for (int j = 0; j < 4; j++) s[i][j] = 0.f;

        if (live) {
            for (int f = 0; f < PHI; f += 4) {
                float4 k0 = *(const float4*)&sK[(n0+0)*PLD + f];
                float4 k1 = *(const float4*)&sK[(n0+1)*PLD + f];
                float4 k2 = *(const float4*)&sK[(n0+2)*PLD + f];
                float4 k3 = *(const float4*)&sK[(n0+3)*PLD + f];
                #pragma unroll
                for (int i = 0; i < 8; i++) {
                    float4 q4 = *(const float4*)&sQ[(m0+i)*PLD + f];
                    DOT4(s[i][0], q4, k0); DOT4(s[i][1], q4, k1);
                    DOT4(s[i][2], q4, k2); DOT4(s[i][3], q4, k3);
                }
            }
        }
        #pragma unroll
        for (int i = 0; i < 8; i++) {
            const int m = m0 + i;
            #pragma unroll
            for (int j = 0; j < 4; j++) {
                float sv_ = (nbase + j <= m) ? s[i][j] : 0.f;
                sS[m*VLD + n0 + j] = sv_;
            }
        }
        __syncthreads();

        if (live || tx == 0) {
            float dsum[8];
            #pragma unroll
            for (int i = 0; i < 8; i++) dsum[i] = 0.f;
            for (int n = 0; n < 64; n += 4) {
                float4 v0 = *(const float4*)&sV[(n+0)*VLD + d0];
                float4 v1 = *(const float4*)&sV[(n+1)*VLD + d0];
                float4 v2 = *(const float4*)&sV[(n+2)*VLD + d0];
                float4 v3 = *(const float4*)&sV[(n+3)*VLD + d0];
                #pragma unroll
                for (int i = 0; i < 8; i++) {
                    float4 s4 = *(const float4*)&sS[(m0+i)*VLD + n];
                    OP4(y[i], s4.x, v0); OP4(y[i], s4.y, v1);
                    OP4(y[i], s4.z, v2); OP4(y[i], s4.w, v3);
                    if (tx == 0) dsum[i] += s4.x + s4.y + s4.z + s4.w;
                }
            }
            if (tx == 0) {
                #pragma unroll
                for (int i = 0; i < 8; i++) sDen[m0+i] += dsum[i];
            }
        }
    }
    __syncthreads();

    float* orow = out + tok0*DN;
    #pragma unroll
    for (int i = 0; i < 8; i++) {
        const float inv = 1.f / (sDen[m0+i] + EPSF);
        #pragma unroll
        for (int j = 0; j < 4; j++)
            orow[(size_t)(m0+i)*DN + d0 + j] = y[i][j] * inv;
    }
}

// ============================================================================
extern "C" void kernel_launch(void* const* d_in, const int* in_sizes, int n_in,
                              void* d_out, int out_size)
{
    const float* q  = (const float*)d_in[0];
    const float* k  = (const float*)d_in[1];
    const float* v  = (const float*)d_in[2];
    const float* Wq = (const float*)d_in[3];
    const float* Wk = (const float*)d_in[4];
    const int*   li = (const int*)d_in[5];
    float* out = (float*)d_out;

    const int SMEM_STATE = (CK*PLD + CK*VLD) * 4;                                        // 102400 B
    const int SMEM_OUT   = (CK*PLD + PHI*VLD + 64*PLD + 64*VLD + CK*VLD + PHI + CK) * 4; // 189440 B
    cudaFuncSetAttribute(state_kernel, cudaFuncAttributeMaxDynamicSharedMemorySize, SMEM_STATE);
    cudaFuncSetAttribute(out_kernel,   cudaFuncAttributeMaxDynamicSharedMemorySize, SMEM_OUT);

    dim3 g1(LN/32, BH, 2);
    fmap_kernel<<<g1, 256>>>(q, k, Wq, Wk, li);

    dim3 g2(NC, BH);
    state_kernel<<<g2, 256, SMEM_STATE>>>(v);
    prefix_kernel<<<dim3(1024, 2), 256>>>();
    out_kernel<<<g2, 256, SMEM_OUT>>>(v, out);
}

// round 5
// speedup vs baseline: 1.6028x; 1.1693x over previous
#include <cuda_runtime.h>

// ---------------- problem constants (from reference setup_inputs) ----------
#define BN   2
#define HN   16
#define BH   32          // B*H
#define LN   2048
#define DN   64
#define FN   64
#define PHI  128         // 2F
#define CK   128         // chunk length
#define NC   16          // LN/CK
#define EPSF 1e-12f

#define PLD  132         // padded leading dim for [*, 128] tiles (132 % 32 = 4 -> bank-walk)
#define VLD  68          // padded leading dim for [*, 64] tiles

// ---------------- scratch (static device globals; no allocation) -----------
__device__ float g_phiq[(size_t)BH*LN*PHI];      // 33.5 MB
__device__ float g_phik[(size_t)BH*LN*PHI];      // 33.5 MB
__device__ float g_state[(size_t)BH*NC*PHI*DN];  // 16.8 MB  per-chunk K^T V
__device__ float g_zst  [(size_t)BH*NC*PHI];
__device__ float g_spref[(size_t)BH*NC*PHI*DN];
__device__ float g_zpref[(size_t)BH*NC*PHI];

#define DOT4(acc, a4, b4) { (acc) += (a4).x*(b4).x + (a4).y*(b4).y + (a4).z*(b4).z + (a4).w*(b4).w; }
#define OP4(yrow, a, b4)  { (yrow)[0] += (a)*(b4).x; (yrow)[1] += (a)*(b4).y; (yrow)[2] += (a)*(b4).z; (yrow)[3] += (a)*(b4).w; }

// ============================================================================
// Pass 1: hedgehog feature map.  phi = clip([softmax(xW), softmax(-xW)], eps)
// grid (LN/32, BH, 2), block 256 (8 warps). Each warp handles 4 rows.
// ============================================================================
__global__ __launch_bounds__(256) void fmap_kernel(
    const float* __restrict__ q, const float* __restrict__ k,
    const float* __restrict__ Wq, const float* __restrict__ Wk,
    const int* __restrict__ lidx)
{
    __shared__ float sW[DN*FN];      // 16 KB
    __shared__ float sx[32][68];

    const int which = blockIdx.z;
    const float* x = which ? k  : q;
    const float* W = which ? Wk : Wq;

    const int bh  = blockIdx.y;
    const int h   = bh % HN;
    const int tid = threadIdx.x;
    const int li  = lidx[0];

    const float* Wh = W + ((size_t)li*HN + h)*DN*FN;
    for (int i = tid; i < DN*FN/4; i += 256)
        ((float4*)sW)[i] = ((const float4*)Wh)[i];

    const int row0 = blockIdx.x * 32;
    const float* xr = x + ((size_t)bh*LN + row0)*DN;
    for (int i = tid; i < 32*DN/4; i += 256) {
        const int r = i >> 4, c = i & 15;
        *(float4*)&sx[r][c*4] = ((const float4*)xr)[i];
    }
    __syncthreads();

    const int w    = tid >> 5;
    const int lane = tid & 31;

    float o[4][2];
    #pragma unroll
    for (int r = 0; r < 4; r++) { o[r][0] = 0.f; o[r][1] = 0.f; }

    #pragma unroll 4
    for (int d = 0; d < DN; d++) {
        const float w0 = sW[d*FN + lane];
        const float w1 = sW[d*FN + lane + 32];
        #pragma unroll
        for (int r = 0; r < 4; r++) {
            const float xv = sx[w*4 + r][d];
            o[r][0] += xv * w0;
            o[r][1] += xv * w1;
        }
    }

    float* phidst = which ? g_phik : g_phiq;
    #pragma unroll
    for (int r = 0; r < 4; r++) {
        float o0 = o[r][0], o1 = o[r][1];
        float mx = fmaxf(o0, o1), mn = fminf(o0, o1);
        #pragma unroll
        for (int off = 16; off; off >>= 1) {
            mx = fmaxf(mx, __shfl_xor_sync(0xffffffffu, mx, off));
            mn = fminf(mn, __shfl_xor_sync(0xffffffffu, mn, off));
        }
        float e0 = __expf(o0 - mx), e1 = __expf(o1 - mx);   // softmax(o)
        float n0 = __expf(mn - o0), n1 = __expf(mn - o1);   // softmax(-o)
        float se = e0 + e1, sn = n0 + n1;
        #pragma unroll
        for (int off = 16; off; off >>= 1) {
            se += __shfl_xor_sync(0xffffffffu, se, off);
            sn += __shfl_xor_sync(0xffffffffu, sn, off);
        }
        const float ie = 1.f/se, in_ = 1.f/sn;
        float* pr = phidst + ((size_t)bh*LN + row0 + w*4 + r)*PHI;
        pr[lane]      = fmaxf(e0*ie,  EPSF);
        pr[lane + 32] = fmaxf(e1*ie,  EPSF);
        pr[64 + lane] = fmaxf(n0*in_, EPSF);
        pr[96 + lane] = fmaxf(n1*in_, EPSF);
    }
}

// ============================================================================
// Pass 2: per-chunk states  S_c[f][d] = sum_n phi_k[n][f] v[n][d],  z_c[f]
// grid (NC, BH), block 256, dynamic smem 100 KB (2 CTAs/SM)
// ============================================================================
__global__ __launch_bounds__(256) void state_kernel(const float* __restrict__ v)
{
    extern __shared__ float sm[];
    float* sPhi = sm;               // CK*PLD
    float* sV   = sm + CK*PLD;      // CK*VLD
    const int c = blockIdx.x, bh = blockIdx.y, tid = threadIdx.x;
    const size_t tok0 = (size_t)bh*LN + (size_t)c*CK;

    const float* pk = g_phik + tok0*PHI;
    for (int i = tid; i < CK*PHI; i += 256) sPhi[(i>>7)*PLD + (i&127)] = pk[i];
    const float* vr = v + tok0*DN;
    for (int i = tid; i < CK*DN;  i += 256) sV[(i>>6)*VLD + (i&63)]   = vr[i];
    __syncthreads();

    const int f0 = (tid >> 4) * 8, d0 = (tid & 15) * 4;
    float acc[8][4];
    #pragma unroll
    for (int i = 0; i < 8; i++)
        #pragma unroll
        for (int j = 0; j < 4; j++) acc[i][j] = 0.f;

    for (int n = 0; n < CK; n++) {
        float4 a0 = *(const float4*)&sPhi[n*PLD + f0];
        float4 a1 = *(const float4*)&sPhi[n*PLD + f0 + 4];
        float4 vv = *(const float4*)&sV[n*VLD + d0];
        OP4(acc[0], a0.x, vv); OP4(acc[1], a0.y, vv); OP4(acc[2], a0.z, vv); OP4(acc[3], a0.w, vv);
        OP4(acc[4], a1.x, vv); OP4(acc[5], a1.y, vv); OP4(acc[6], a1.z, vv); OP4(acc[7], a1.w, vv);
    }

    float* So = g_state + ((size_t)bh*NC + c)*(PHI*DN);
    #pragma unroll
    for (int i = 0; i < 8; i++)
        #pragma unroll
        for (int j = 0; j < 4; j++)
            So[(f0+i)*DN + d0 + j] = acc[i][j];

    if (tid < PHI) {
        float z = 0.f;
        for (int n = 0; n < CK; n++) z += sPhi[n*PLD + tid];
        g_zst[((size_t)bh*NC + c)*PHI + tid] = z;
    }
}

// ============================================================================
// Pass 2b: exclusive prefix over chunks — fully parallel register scans.
// ============================================================================
__global__ __launch_bounds__(256) void prefix_kernel()
{
    const int t = blockIdx.x * 256 + threadIdx.x;
    if (blockIdx.y == 0) {
        const int bh = t >> 13, idx = t & 8191;
        const size_t base = ((size_t)bh*NC)*(PHI*DN) + idx;
        float vals[NC];
        #pragma unroll
        for (int c = 0; c < NC; c++) vals[c] = g_state[base + (size_t)c*(PHI*DN)];
        float run = 0.f;
        #pragma unroll
        for (int c = 0; c < NC; c++) {
            g_spref[base + (size_t)c*(PHI*DN)] = run;
            run += vals[c];
        }
    } else {
        if (t >= BH*PHI) return;
        const int bh = t >> 7, idx = t & 127;
        const size_t base = ((size_t)bh*NC)*PHI + idx;
        float vals[NC];
        #pragma unroll
        for (int c = 0; c < NC; c++) vals[c] = g_zst[base + (size_t)c*PHI];
        float run = 0.f;
        #pragma unroll
        for (int c = 0; c < NC; c++) {
            g_zpref[base + (size_t)c*PHI] = run;
            run += vals[c];
        }
    }
}

// ============================================================================
// Pass 3: per-chunk output. 512 threads, single 128x128 score pass.
//   Phase A: y(4m x 4d) = phiQ @ S_pref ; den_inter = phiQ . z_pref
//   Phase B: load K (full 128), V (aliases S_pref smem)
//   Phase C: scores s(8m x 4n, n = lane + 32j, conflict-free) ; causal mask;
//            warp-shuffle row sums -> sDen
//   Phase D: stage masked scores over the K smem (aliased)
//   Phase E: y += S @ V ; out = y / (den + eps)
// smem: 128*PLD + 128*VLD + 128*PLD + 256 floats = 171 KB -> 16 warps/SM
// ============================================================================
__global__ __launch_bounds__(512) void out_kernel(
    const float* __restrict__ v, float* __restrict__ out)
{
    extern __shared__ float sm[];
    float* sQ   = sm;                    // 128*PLD              (phi_q)
    float* sSp  = sQ  + CK*PLD;          // 128*VLD   S_pref, then V
    float* sKS  = sSp + PHI*VLD;         // 128*PLD   phi_k, then scores
    float* sZ   = sKS + CK*PLD;          // 128
    float* sDen = sZ  + PHI;             // 128

    const int c = blockIdx.x, bh = blockIdx.y, tid = threadIdx.x;
    const size_t tok0 = (size_t)bh*LN + (size_t)c*CK;

    // ---- load Q [128,128], S_pref [128,64], z_pref ----
    {
        const float4* pq = (const float4*)(g_phiq + tok0*PHI);
        for (int i = tid; i < CK*PHI/4; i += 512) {
            const int r = i >> 5, c4 = i & 31;
            *(float4*)&sQ[r*PLD + c4*4] = pq[i];
        }
        const float4* sp = (const float4*)(g_spref + ((size_t)bh*NC + c)*(PHI*DN));
        for (int i = tid; i < PHI*DN/4; i += 512) {
            const int r = i >> 4, c4 = i & 15;
            *(float4*)&sSp[r*VLD + c4*4] = sp[i];
        }
        if (tid < PHI) sZ[tid] = g_zpref[((size_t)bh*NC + c)*PHI + tid];
    }
    __syncthreads();

    // ---- Phase A: inter-chunk ----
    if (tid < CK) {
        float ds = 0.f;
        #pragma unroll 8
        for (int f = 0; f < PHI; f += 4) {
            float4 q4 = *(const float4*)&sQ[tid*PLD + f];
            float4 z4 = *(const float4*)&sZ[f];
            DOT4(ds, q4, z4);
        }
        sDen[tid] = ds;
    }

    const int tyo = tid >> 4, txo = tid & 15;   // 32 x 16
    const int m0o = tyo * 4, d0 = txo * 4;
    float y[4][4];
    #pragma unroll
    for (int i = 0; i < 4; i++)
        #pragma unroll
        for (int j = 0; j < 4; j++) y[i][j] = 0.f;

    for (int f = 0; f < PHI; f += 4) {
        float4 sp0 = *(const float4*)&sSp[(f+0)*VLD + d0];
        float4 sp1 = *(const float4*)&sSp[(f+1)*VLD + d0];
        float4 sp2 = *(const float4*)&sSp[(f+2)*VLD + d0];
        float4 sp3 = *(const float4*)&sSp[(f+3)*VLD + d0];
        #pragma unroll
        for (int i = 0; i < 4; i++) {
            float4 q4 = *(const float4*)&sQ[(m0o+i)*PLD + f];
            OP4(y[i], q4.x, sp0); OP4(y[i], q4.y, sp1);
            OP4(y[i], q4.z, sp2); OP4(y[i], q4.w, sp3);
        }
    }
    __syncthreads();   // done reading sSp -> V may overwrite

    // ---- Phase B: load K [128,128] and V [128,64] (V aliases sSp) ----
    {
        const float4* pk = (const float4*)(g_phik + tok0*PHI);
        for (int i = tid; i < CK*PHI/4; i += 512) {
            const int r = i >> 5, c4 = i & 31;
            *(float4*)&sKS[r*PLD + c4*4] = pk[i];
        }
        const float4* vr = (const float4*)(v + tok0*DN);
        for (int i = tid; i < CK*DN/4; i += 512) {
            const int r = i >> 4, c4 = i & 15;
            *(float4*)&sSp[r*VLD + c4*4] = vr[i];
        }
    }
    __syncthreads();

    // ---- Phase C: scores. warp w owns m rows [w*8, w*8+8); lane covers
    //      n in {lane, lane+32, lane+64, lane+96}  (conflict-free LDS) ----
    const int w    = tid >> 5;
    const int lane = tid & 31;
    const int m0   = w * 8;

    float s[8][4];
    #pragma unroll
    for (int i = 0; i < 8; i++)
        #pragma unroll
        for (int j = 0; j < 4; j++) s[i][j] = 0.f;

    for (int f = 0; f < PHI; f += 4) {
        float4 k0 = *(const float4*)&sKS[(lane      )*PLD + f];
        float4 k1 = *(const float4*)&sKS[(lane + 32 )*PLD + f];
        float4 k2 = *(const float4*)&sKS[(lane + 64 )*PLD + f];
        float4 k3 = *(const float4*)&sKS[(lane + 96 )*PLD + f];
        #pragma unroll
        for (int i = 0; i < 8; i++) {
            float4 q4 = *(const float4*)&sQ[(m0+i)*PLD + f];
            DOT4(s[i][0], q4, k0); DOT4(s[i][1], q4, k1);
            DOT4(s[i][2], q4, k2); DOT4(s[i][3], q4, k3);
        }
    }

    // causal mask + per-row warp reduction into sDen
    #pragma unroll
    for (int i = 0; i < 8; i++) {
        const int m = m0 + i;
        float ds = 0.f;
        #pragma unroll
        for (int j = 0; j < 4; j++) {
            const float sv_ = (lane + 32*j <= m) ? s[i][j] : 0.f;
            s[i][j] = sv_;
            ds += sv_;
        }
        #pragma unroll
        for (int off = 16; off; off >>= 1)
            ds += __shfl_xor_sync(0xffffffffu, ds, off);
        if (lane == 0) sDen[m] += ds;   // warp w exclusively owns rows m0..m0+7
    }
    __syncthreads();   // all K reads done -> scores may overwrite sKS

    // ---- Phase D: stage masked scores over K smem ----
    #pragma unroll
    for (int i = 0; i < 8; i++) {
        #pragma unroll
        for (int j = 0; j < 4; j++)
            sKS[(m0+i)*PLD + lane + 32*j] = s[i][j];
    }
    __syncthreads();

    // ---- Phase E: y += S @ V ----
    for (int n = 0; n < CK; n += 4) {
        float4 v0 = *(const float4*)&sSp[(n+0)*VLD + d0];
        float4 v1 = *(const float4*)&sSp[(n+1)*VLD + d0];
        float4 v2 = *(const float4*)&sSp[(n+2)*VLD + d0];
        float4 v3 = *(const float4*)&sSp[(n+3)*VLD + d0];
        #pragma unroll
        for (int i = 0; i < 4; i++) {
            float4 s4 = *(const float4*)&sKS[(m0o+i)*PLD + n];
            OP4(y[i], s4.x, v0); OP4(y[i], s4.y, v1);
            OP4(y[i], s4.z, v2); OP4(y[i], s4.w, v3);
        }
    }

    float* orow = out + tok0*DN;
    #pragma unroll
    for (int i = 0; i < 4; i++) {
        const float inv = 1.f / (sDen[m0o+i] + EPSF);
        #pragma unroll
        for (int j = 0; j < 4; j++)
            orow[(size_t)(m0o+i)*DN + d0 + j] = y[i][j] * inv;
    }
}

// ============================================================================
extern "C" void kernel_launch(void* const* d_in, const int* in_sizes, int n_in,
                              void* d_out, int out_size)
{
    const float* q  = (const float*)d_in[0];
    const float* k  = (const float*)d_in[1];
    const float* v  = (const float*)d_in[2];
    const float* Wq = (const float*)d_in[3];
    const float* Wk = (const float*)d_in[4];
    const int*   li = (const int*)d_in[5];
    float* out = (float*)d_out;

    const int SMEM_STATE = (CK*PLD + CK*VLD) * 4;                       // 102400 B
    const int SMEM_OUT   = (CK*PLD + PHI*VLD + CK*PLD + PHI + CK) * 4;  // 171008 B
    cudaFuncSetAttribute(state_kernel, cudaFuncAttributeMaxDynamicSharedMemorySize, SMEM_STATE);
    cudaFuncSetAttribute(out_kernel,   cudaFuncAttributeMaxDynamicSharedMemorySize, SMEM_OUT);

    dim3 g1(LN/32, BH, 2);
    fmap_kernel<<<g1, 256>>>(q, k, Wq, Wk, li);

    dim3 g2(NC, BH);
    state_kernel<<<g2, 256, SMEM_STATE>>>(v);
    prefix_kernel<<<dim3(1024, 2), 256>>>();
    out_kernel<<<g2, 512, SMEM_OUT>>>(v, out);
}

// round 7
// speedup vs baseline: 1.7883x; 1.1157x over previous
#include <cuda_runtime.h>

// ---------------- problem constants (from reference setup_inputs) ----------
#define BN   2
#define HN   16
#define BH   32          // B*H
#define LN   2048
#define DN   64
#define FN   64
#define PHI  128         // 2F
#define CK   128         // chunk length
#define NC   16          // LN/CK
#define EPSF 1e-12f

#define PLD  132         // padded leading dim for [*, 128] tiles
#define VLD  68          // padded leading dim for [*, 64] tiles

typedef unsigned long long u64p;   // packed float2 in one 64-bit reg

__device__ __forceinline__ u64p pk2(float a, float b) {
    u64p r; asm("mov.b64 %0, {%1, %2};" : "=l"(r) : "f"(a), "f"(b)); return r;
}
__device__ __forceinline__ void fma2(u64p& d, u64p a, u64p b) {
    asm("fma.rn.f32x2 %0, %1, %2, %0;" : "+l"(d) : "l"(a), "l"(b));
}
__device__ __forceinline__ float2 upk(u64p p) {
    float2 v; asm("mov.b64 {%0, %1}, %2;" : "=f"(v.x), "=f"(v.y) : "l"(p)); return v;
}

// ---------------- scratch (static device globals; no allocation) -----------
__device__ float g_phiq[(size_t)BH*LN*PHI];      // 33.5 MB
__device__ float g_phik[(size_t)BH*LN*PHI];      // 33.5 MB
__device__ float g_state[(size_t)BH*NC*PHI*DN];  // 16.8 MB  per-chunk K^T V
__device__ float g_zst  [(size_t)BH*NC*PHI];
__device__ float g_spref[(size_t)BH*NC*PHI*DN];
__device__ float g_zpref[(size_t)BH*NC*PHI];

#define DOT4(acc, a4, b4) { (acc) += (a4).x*(b4).x + (a4).y*(b4).y + (a4).z*(b4).z + (a4).w*(b4).w; }

// ============================================================================
// Pass 1: hedgehog feature map.  phi = clip([softmax(xW), softmax(-xW)], eps)
// grid (LN/32, BH, 2), block 256 (8 warps). Each warp handles 4 rows.
// ============================================================================
__global__ __launch_bounds__(256) void fmap_kernel(
    const float* __restrict__ q, const float* __restrict__ k,
    const float* __restrict__ Wq, const float* __restrict__ Wk,
    const int* __restrict__ lidx)
{
    __shared__ float sW[DN*FN];      // 16 KB
    __shared__ float sx[32][68];

    const int which = blockIdx.z;
    const float* x = which ? k  : q;
    const float* W = which ? Wk : Wq;

    const int bh  = blockIdx.y;
    const int h   = bh % HN;
    const int tid = threadIdx.x;
    const int li  = lidx[0];

    const float* Wh = W + ((size_t)li*HN + h)*DN*FN;
    for (int i = tid; i < DN*FN/4; i += 256)
        ((float4*)sW)[i] = ((const float4*)Wh)[i];

    const int row0 = blockIdx.x * 32;
    const float* xr = x + ((size_t)bh*LN + row0)*DN;
    for (int i = tid; i < 32*DN/4; i += 256) {
        const int r = i >> 4, c = i & 15;
        *(float4*)&sx[r][c*4] = ((const float4*)xr)[i];
    }
    __syncthreads();

    const int w    = tid >> 5;
    const int lane = tid & 31;

    float o[4][2];
    #pragma unroll
    for (int r = 0; r < 4; r++) { o[r][0] = 0.f; o[r][1] = 0.f; }

    #pragma unroll 4
    for (int d = 0; d < DN; d++) {
        const float w0 = sW[d*FN + lane];
        const float w1 = sW[d*FN + lane + 32];
        #pragma unroll
        for (int r = 0; r < 4; r++) {
            const float xv = sx[w*4 + r][d];
            o[r][0] += xv * w0;
            o[r][1] += xv * w1;
        }
    }

    float* phidst = which ? g_phik : g_phiq;
    #pragma unroll
    for (int r = 0; r < 4; r++) {
        float o0 = o[r][0], o1 = o[r][1];
        float mx = fmaxf(o0, o1), mn = fminf(o0, o1);
        #pragma unroll
        for (int off = 16; off; off >>= 1) {
            mx = fmaxf(mx, __shfl_xor_sync(0xffffffffu, mx, off));
            mn = fminf(mn, __shfl_xor_sync(0xffffffffu, mn, off));
        }
        float e0 = __expf(o0 - mx), e1 = __expf(o1 - mx);   // softmax(o)
        float n0 = __expf(mn - o0), n1 = __expf(mn - o1);   // softmax(-o)
        float se = e0 + e1, sn = n0 + n1;
        #pragma unroll
        for (int off = 16; off; off >>= 1) {
            se += __shfl_xor_sync(0xffffffffu, se, off);
            sn += __shfl_xor_sync(0xffffffffu, sn, off);
        }
        const float ie = 1.f/se, in_ = 1.f/sn;
        float* pr = phidst + ((size_t)bh*LN + row0 + w*4 + r)*PHI;
        pr[lane]      = fmaxf(e0*ie,  EPSF);
        pr[lane + 32] = fmaxf(e1*ie,  EPSF);
        pr[64 + lane] = fmaxf(n0*in_, EPSF);
        pr[96 + lane] = fmaxf(n1*in_, EPSF);
    }
}

// ============================================================================
// Pass 2: per-chunk states  S_c[f][d] = sum_n phi_k[n][f] v[n][d],  z_c[f]
// grid (NC, BH), block 256, dynamic smem 100 KB. Packed f32x2 accumulators.
// ============================================================================
__global__ __launch_bounds__(256) void state_kernel(const float* __restrict__ v)
{
    extern __shared__ float sm[];
    float* sPhi = sm;               // CK*PLD
    float* sV   = sm + CK*PLD;      // CK*VLD
    const int c = blockIdx.x, bh = blockIdx.y, tid = threadIdx.x;
    const size_t tok0 = (size_t)bh*LN + (size_t)c*CK;

    const float* pk = g_phik + tok0*PHI;
    for (int i = tid; i < CK*PHI; i += 256) sPhi[(i>>7)*PLD + (i&127)] = pk[i];
    const float* vr = v + tok0*DN;
    for (int i = tid; i < CK*DN;  i += 256) sV[(i>>6)*VLD + (i&63)]   = vr[i];
    __syncthreads();

    const int f0 = (tid >> 4) * 8, d0 = (tid & 15) * 4;
    u64p acc[8][2];
    #pragma unroll
    for (int i = 0; i < 8; i++) { acc[i][0] = 0ull; acc[i][1] = 0ull; }

    for (int n = 0; n < CK; n++) {
        float4 a0 = *(const float4*)&sPhi[n*PLD + f0];
        float4 a1 = *(const float4*)&sPhi[n*PLD + f0 + 4];
        float4 vv = *(const float4*)&sV[n*VLD + d0];
        const u64p vl = pk2(vv.x, vv.y), vh = pk2(vv.z, vv.w);
        u64p aa;
        aa = pk2(a0.x, a0.x); fma2(acc[0][0], aa, vl); fma2(acc[0][1], aa, vh);
        aa = pk2(a0.y, a0.y); fma2(acc[1][0], aa, vl); fma2(acc[1][1], aa, vh);
        aa = pk2(a0.z, a0.z); fma2(acc[2][0], aa, vl); fma2(acc[2][1], aa, vh);
        aa = pk2(a0.w, a0.w); fma2(acc[3][0], aa, vl); fma2(acc[3][1], aa, vh);
        aa = pk2(a1.x, a1.x); fma2(acc[4][0], aa, vl); fma2(acc[4][1], aa, vh);
        aa = pk2(a1.y, a1.y); fma2(acc[5][0], aa, vl); fma2(acc[5][1], aa, vh);
        aa = pk2(a1.z, a1.z); fma2(acc[6][0], aa, vl); fma2(acc[6][1], aa, vh);
        aa = pk2(a1.w, a1.w); fma2(acc[7][0], aa, vl); fma2(acc[7][1], aa, vh);
    }

    float* So = g_state + ((size_t)bh*NC + c)*(PHI*DN);
    #pragma unroll
    for (int i = 0; i < 8; i++) {
        float2 p0 = upk(acc[i][0]), p1 = upk(acc[i][1]);
        So[(f0+i)*DN + d0 + 0] = p0.x;
        So[(f0+i)*DN + d0 + 1] = p0.y;
        So[(f0+i)*DN + d0 + 2] = p1.x;
        So[(f0+i)*DN + d0 + 3] = p1.y;
    }

    if (tid < PHI) {
        float z = 0.f;
        for (int n = 0; n < CK; n++) z += sPhi[n*PLD + tid];
        g_zst[((size_t)bh*NC + c)*PHI + tid] = z;
    }
}

// ============================================================================
// Pass 2b: exclusive prefix over chunks — fully parallel register scans.
// ============================================================================
__global__ __launch_bounds__(256) void prefix_kernel()
{
    const int t = blockIdx.x * 256 + threadIdx.x;
    if (blockIdx.y == 0) {
        const int bh = t >> 13, idx = t & 8191;
        const size_t base = ((size_t)bh*NC)*(PHI*DN) + idx;
        float vals[NC];
        #pragma unroll
        for (int c = 0; c < NC; c++) vals[c] = g_state[base + (size_t)c*(PHI*DN)];
        float run = 0.f;
        #pragma unroll
        for (int c = 0; c < NC; c++) {
            g_spref[base + (size_t)c*(PHI*DN)] = run;
            run += vals[c];
        }
    } else {
        if (t >= BH*PHI) return;
        const int bh = t >> 7, idx = t & 127;
        const size_t base = ((size_t)bh*NC)*PHI + idx;
        float vals[NC];
        #pragma unroll
        for (int c = 0; c < NC; c++) vals[c] = g_zst[base + (size_t)c*PHI];
        float run = 0.f;
        #pragma unroll
        for (int c = 0; c < NC; c++) {
            g_zpref[base + (size_t)c*PHI] = run;
            run += vals[c];
        }
    }
}

// ============================================================================
// Pass 3: per-chunk output. 512 threads, packed f32x2 FMA throughout.
// ============================================================================
__global__ __launch_bounds__(512) void out_kernel(
    const float* __restrict__ v, float* __restrict__ out)
{
    extern __shared__ float sm[];
    float* sQ   = sm;                    // 128*PLD              (phi_q)
    float* sSp  = sQ  + CK*PLD;          // 128*VLD   S_pref, then V
    float* sKS  = sSp + PHI*VLD;         // 128*PLD   phi_k, then scores
    float* sZ   = sKS + CK*PLD;          // 128
    float* sDen = sZ  + PHI;             // 128

    const int c = blockIdx.x, bh = blockIdx.y, tid = threadIdx.x;
    const size_t tok0 = (size_t)bh*LN + (size_t)c*CK;

    // ---- load Q [128,128], S_pref [128,64], z_pref ----
    {
        const float4* pq = (const float4*)(g_phiq + tok0*PHI);
        for (int i = tid; i < CK*PHI/4; i += 512) {
            const int r = i >> 5, c4 = i & 31;
            *(float4*)&sQ[r*PLD + c4*4] = pq[i];
        }
        const float4* sp = (const float4*)(g_spref + ((size_t)bh*NC + c)*(PHI*DN));
        for (int i = tid; i < PHI*DN/4; i += 512) {
            const int r = i >> 4, c4 = i & 15;
            *(float4*)&sSp[r*VLD + c4*4] = sp[i];
        }
        if (tid < PHI) sZ[tid] = g_zpref[((size_t)bh*NC + c)*PHI + tid];
    }
    __syncthreads();

    // ---- Phase A: inter-chunk denominator (packed dot) ----
    if (tid < CK) {
        u64p ds2 = 0ull;
        #pragma unroll 8
        for (int f = 0; f < PHI; f += 4) {
            float4 q4 = *(const float4*)&sQ[tid*PLD + f];
            float4 z4 = *(const float4*)&sZ[f];
            fma2(ds2, pk2(q4.x, q4.y), pk2(z4.x, z4.y));
            fma2(ds2, pk2(q4.z, q4.w), pk2(z4.z, z4.w));
        }
        float2 dp = upk(ds2);
        sDen[tid] = dp.x + dp.y;
    }

    const int tyo = tid >> 4, txo = tid & 15;   // 32 x 16
    const int m0o = tyo * 4, d0 = txo * 4;
    u64p y2[4][2];
    #pragma unroll
    for (int i = 0; i < 4; i++) { y2[i][0] = 0ull; y2[i][1] = 0ull; }

    // ---- Phase A2: y = phiQ @ S_pref (packed broadcast form) ----
    for (int f = 0; f < PHI; f += 4) {
        float4 sp0 = *(const float4*)&sSp[(f+0)*VLD + d0];
        float4 sp1 = *(const float4*)&sSp[(f+1)*VLD + d0];
        float4 sp2 = *(const float4*)&sSp[(f+2)*VLD + d0];
        float4 sp3 = *(const float4*)&sSp[(f+3)*VLD + d0];
        const u64p p0l = pk2(sp0.x,sp0.y), p0h = pk2(sp0.z,sp0.w);
        const u64p p1l = pk2(sp1.x,sp1.y), p1h = pk2(sp1.z,sp1.w);
        const u64p p2l = pk2(sp2.x,sp2.y), p2h = pk2(sp2.z,sp2.w);
        const u64p p3l = pk2(sp3.x,sp3.y), p3h = pk2(sp3.z,sp3.w);
        #pragma unroll
        for (int i = 0; i < 4; i++) {
            float4 q4 = *(const float4*)&sQ[(m0o+i)*PLD + f];
            u64p aa;
            aa = pk2(q4.x, q4.x); fma2(y2[i][0], aa, p0l); fma2(y2[i][1], aa, p0h);
            aa = pk2(q4.y, q4.y); fma2(y2[i][0], aa, p1l); fma2(y2[i][1], aa, p1h);
            aa = pk2(q4.z, q4.z); fma2(y2[i][0], aa, p2l); fma2(y2[i][1], aa, p2h);
            aa = pk2(q4.w, q4.w); fma2(y2[i][0], aa, p3l); fma2(y2[i][1], aa, p3h);
        }
    }
    __syncthreads();   // done reading sSp -> V may overwrite

    // ---- Phase B: load K [128,128] and V [128,64] (V aliases sSp) ----
    {
        const float4* pk = (const float4*)(g_phik + tok0*PHI);
        for (int i = tid; i < CK*PHI/4; i += 512) {
            const int r = i >> 5, c4 = i & 31;
            *(float4*)&sKS[r*PLD + c4*4] = pk[i];
        }
        const float4* vr = (const float4*)(v + tok0*DN);
        for (int i = tid; i < CK*DN/4; i += 512) {
            const int r = i >> 4, c4 = i & 15;
            *(float4*)&sSp[r*VLD + c4*4] = vr[i];
        }
    }
    __syncthreads();

    // ---- Phase C: scores via packed-pair dots. warp w owns m rows
    //      [w*8, w*8+8); lane covers n in {lane, lane+32, lane+64, lane+96}.
    const int w    = tid >> 5;
    const int lane = tid & 31;
    const int m0   = w * 8;

    u64p s2[8][4];
    #pragma unroll
    for (int i = 0; i < 8; i++)
        #pragma unroll
        for (int j = 0; j < 4; j++) s2[i][j] = 0ull;

    for (int f = 0; f < PHI; f += 4) {
        float4 k0 = *(const float4*)&sKS[(lane      )*PLD + f];
        float4 k1 = *(const float4*)&sKS[(lane + 32 )*PLD + f];
        float4 k2 = *(const float4*)&sKS[(lane + 64 )*PLD + f];
        float4 k3 = *(const float4*)&sKS[(lane + 96 )*PLD + f];
        const u64p k0l = pk2(k0.x,k0.y), k0h = pk2(k0.z,k0.w);
        const u64p k1l = pk2(k1.x,k1.y), k1h = pk2(k1.z,k1.w);
        const u64p k2l = pk2(k2.x,k2.y), k2h = pk2(k2.z,k2.w);
        const u64p k3l = pk2(k3.x,k3.y), k3h = pk2(k3.z,k3.w);
        #pragma unroll
        for (int i = 0; i < 8; i++) {
            float4 q4 = *(const float4*)&sQ[(m0+i)*PLD + f];
            const u64p ql = pk2(q4.x,q4.y), qh = pk2(q4.z,q4.w);
            fma2(s2[i][0], ql, k0l); fma2(s2[i][0], qh, k0h);
            fma2(s2[i][1], ql, k1l); fma2(s2[i][1], qh, k1h);
            fma2(s2[i][2], ql, k2l); fma2(s2[i][2], qh, k2h);
            fma2(s2[i][3], ql, k3l); fma2(s2[i][3], qh, k3h);
        }
    }

    // horizontal sum, causal mask, per-row warp reduction into sDen
    float s[8][4];
    #pragma unroll
    for (int i = 0; i < 8; i++) {
        const int m = m0 + i;
        float ds = 0.f;
        #pragma unroll
        for (int j = 0; j < 4; j++) {
            float2 p = upk(s2[i][j]);
            const float sv_ = (lane + 32*j <= m) ? (p.x + p.y) : 0.f;
            s[i][j] = sv_;
            ds += sv_;
        }
        #pragma unroll
        for (int off = 16; off; off >>= 1)
            ds += __shfl_xor_sync(0xffffffffu, ds, off);
        if (lane == 0) sDen[m] += ds;   // warp w exclusively owns rows m0..m0+7
    }
    __syncthreads();   // all K reads done -> scores may overwrite sKS

    // ---- Phase D: stage masked scores over K smem ----
    #pragma unroll
    for (int i = 0; i < 8; i++) {
        #pragma unroll
        for (int j = 0; j < 4; j++)
            sKS[(m0+i)*PLD + lane + 32*j] = s[i][j];
    }
    __syncthreads();

    // ---- Phase E: y += S @ V (packed broadcast form) ----
    for (int n = 0; n < CK; n += 4) {
        float4 v0 = *(const float4*)&sSp[(n+0)*VLD + d0];
        float4 v1 = *(const float4*)&sSp[(n+1)*VLD + d0];
        float4 v2 = *(const float4*)&sSp[(n+2)*VLD + d0];
        float4 v3 = *(const float4*)&sSp[(n+3)*VLD + d0];
        const u64p v0l = pk2(v0.x,v0.y), v0h = pk2(v0.z,v0.w);
        const u64p v1l = pk2(v1.x,v1.y), v1h = pk2(v1.z,v1.w);
        const u64p v2l = pk2(v2.x,v2.y), v2h = pk2(v2.z,v2.w);
        const u64p v3l = pk2(v3.x,v3.y), v3h = pk2(v3.z,v3.w);
        #pragma unroll
        for (int i = 0; i < 4; i++) {
            float4 s4 = *(const float4*)&sKS[(m0o+i)*PLD + n];
            u64p aa;
            aa = pk2(s4.x, s4.x); fma2(y2[i][0], aa, v0l); fma2(y2[i][1], aa, v0h);
            aa = pk2(s4.y, s4.y); fma2(y2[i][0], aa, v1l); fma2(y2[i][1], aa, v1h);
            aa = pk2(s4.z, s4.z); fma2(y2[i][0], aa, v2l); fma2(y2[i][1], aa, v2h);
            aa = pk2(s4.w, s4.w); fma2(y2[i][0], aa, v3l); fma2(y2[i][1], aa, v3h);
        }
    }

    float* orow = out + tok0*DN;
    #pragma unroll
    for (int i = 0; i < 4; i++) {
        const float inv = 1.f / (sDen[m0o+i] + EPSF);
        float2 p0 = upk(y2[i][0]), p1 = upk(y2[i][1]);
        orow[(size_t)(m0o+i)*DN + d0 + 0] = p0.x * inv;
        orow[(size_t)(m0o+i)*DN + d0 + 1] = p0.y * inv;
        orow[(size_t)(m0o+i)*DN + d0 + 2] = p1.x * inv;
        orow[(size_t)(m0o+i)*DN + d0 + 3] = p1.y * inv;
    }
}

// ============================================================================
extern "C" void kernel_launch(void* const* d_in, const int* in_sizes, int n_in,
                              void* d_out, int out_size)
{
    const float* q  = (const float*)d_in[0];
    const float* k  = (const float*)d_in[1];
    const float* v  = (const float*)d_in[2];
    const float* Wq = (const float*)d_in[3];
    const float* Wk = (const float*)d_in[4];
    const int*   li = (const int*)d_in[5];
    float* out = (float*)d_out;

    const int SMEM_STATE = (CK*PLD + CK*VLD) * 4;                       // 102400 B
    const int SMEM_OUT   = (CK*PLD + PHI*VLD + CK*PLD + PHI + CK) * 4;  // 171008 B
    cudaFuncSetAttribute(state_kernel, cudaFuncAttributeMaxDynamicSharedMemorySize, SMEM_STATE);
    cudaFuncSetAttribute(out_kernel,   cudaFuncAttributeMaxDynamicSharedMemorySize, SMEM_OUT);

    dim3 g1(LN/32, BH, 2);
    fmap_kernel<<<g1, 256>>>(q, k, Wq, Wk, li);

    dim3 g2(NC, BH);
    state_kernel<<<g2, 256, SMEM_STATE>>>(v);
    prefix_kernel<<<dim3(1024, 2), 256>>>();
    out_kernel<<<g2, 512, SMEM_OUT>>>(v, out);
}

// round 9
// speedup vs baseline: 1.9881x; 1.1118x over previous
#include <cuda_runtime.h>

// ---------------- problem constants (from reference setup_inputs) ----------
#define BN   2
#define HN   16
#define BH   32          // B*H
#define LN   2048
#define DN   64
#define FN   64
#define PHI  128         // 2F
#define CK   128         // chunk length
#define NC   16          // LN/CK
#define EPSF 1e-12f

#define PLD  132         // padded leading dim for [*, 128] tiles
#define VLD  68          // padded leading dim for [*, 64] tiles

typedef unsigned long long u64p;   // packed float2 in one 64-bit reg

__device__ __forceinline__ u64p pk2(float a, float b) {
    u64p r; asm("mov.b64 %0, {%1, %2};" : "=l"(r) : "f"(a), "f"(b)); return r;
}
__device__ __forceinline__ void fma2(u64p& d, u64p a, u64p b) {
    asm("fma.rn.f32x2 %0, %1, %2, %0;" : "+l"(d) : "l"(a), "l"(b));
}
__device__ __forceinline__ float2 upk(u64p p) {
    float2 v; asm("mov.b64 {%0, %1}, %2;" : "=f"(v.x), "=f"(v.y) : "l"(p)); return v;
}

// ---------------- scratch (static device globals; no allocation) -----------
__device__ float g_phiq[(size_t)BH*LN*PHI];      // 33.5 MB
__device__ float g_phik[(size_t)BH*LN*PHI];      // 33.5 MB
__device__ float g_state[(size_t)BH*NC*PHI*DN];  // 16.8 MB  per-chunk K^T V
__device__ float g_zst  [(size_t)BH*NC*PHI];
__device__ float g_spref[(size_t)BH*NC*PHI*DN];
__device__ float g_zpref[(size_t)BH*NC*PHI];

// ============================================================================
// Pass 1: hedgehog feature map.  phi = clip([softmax(xW), softmax(-xW)], eps)
// grid (LN/32, BH, 2), block 256 (8 warps). Each warp handles 4 rows.
// ============================================================================
__global__ __launch_bounds__(256) void fmap_kernel(
    const float* __restrict__ q, const float* __restrict__ k,
    const float* __restrict__ Wq, const float* __restrict__ Wk,
    const int* __restrict__ lidx)
{
    __shared__ float sW[DN*FN];      // 16 KB
    __shared__ float sx[32][68];

    const int which = blockIdx.z;
    const float* x = which ? k  : q;
    const float* W = which ? Wk : Wq;

    const int bh  = blockIdx.y;
    const int h   = bh % HN;
    const int tid = threadIdx.x;
    const int li  = lidx[0];

    const float* Wh = W + ((size_t)li*HN + h)*DN*FN;
    for (int i = tid; i < DN*FN/4; i += 256)
        ((float4*)sW)[i] = ((const float4*)Wh)[i];

    const int row0 = blockIdx.x * 32;
    const float* xr = x + ((size_t)bh*LN + row0)*DN;
    for (int i = tid; i < 32*DN/4; i += 256) {
        const int r = i >> 4, c = i & 15;
        *(float4*)&sx[r][c*4] = ((const float4*)xr)[i];
    }
    __syncthreads();

    const int w    = tid >> 5;
    const int lane = tid & 31;

    float o[4][2];
    #pragma unroll
    for (int r = 0; r < 4; r++) { o[r][0] = 0.f; o[r][1] = 0.f; }

    #pragma unroll 4
    for (int d = 0; d < DN; d++) {
        const float w0 = sW[d*FN + lane];
        const float w1 = sW[d*FN + lane + 32];
        #pragma unroll
        for (int r = 0; r < 4; r++) {
            const float xv = sx[w*4 + r][d];
            o[r][0] += xv * w0;
            o[r][1] += xv * w1;
        }
    }

    float* phidst = which ? g_phik : g_phiq;
    #pragma unroll
    for (int r = 0; r < 4; r++) {
        float o0 = o[r][0], o1 = o[r][1];
        float mx = fmaxf(o0, o1), mn = fminf(o0, o1);
        #pragma unroll
        for (int off = 16; off; off >>= 1) {
            mx = fmaxf(mx, __shfl_xor_sync(0xffffffffu, mx, off));
            mn = fminf(mn, __shfl_xor_sync(0xffffffffu, mn, off));
        }
        float e0 = __expf(o0 - mx), e1 = __expf(o1 - mx);   // softmax(o)
        float n0 = __expf(mn - o0), n1 = __expf(mn - o1);   // softmax(-o)
        float se = e0 + e1, sn = n0 + n1;
        #pragma unroll
        for (int off = 16; off; off >>= 1) {
            se += __shfl_xor_sync(0xffffffffu, se, off);
            sn += __shfl_xor_sync(0xffffffffu, sn, off);
        }
        const float ie = 1.f/se, in_ = 1.f/sn;
        float* pr = phidst + ((size_t)bh*LN + row0 + w*4 + r)*PHI;
        pr[lane]      = fmaxf(e0*ie,  EPSF);
        pr[lane + 32] = fmaxf(e1*ie,  EPSF);
        pr[64 + lane] = fmaxf(n0*in_, EPSF);
        pr[96 + lane] = fmaxf(n1*in_, EPSF);
    }
}

// ============================================================================
// Pass 2: per-chunk states  S_c[f][d] = sum_n phi_k[n][f] v[n][d],  z_c[f]
// grid (NC, BH), block 256, dynamic smem 100 KB. Packed f32x2 accumulators.
// ============================================================================
__global__ __launch_bounds__(256) void state_kernel(const float* __restrict__ v)
{
    extern __shared__ float sm[];
    float* sPhi = sm;               // CK*PLD
    float* sV   = sm + CK*PLD;      // CK*VLD
    const int c = blockIdx.x, bh = blockIdx.y, tid = threadIdx.x;
    const size_t tok0 = (size_t)bh*LN + (size_t)c*CK;

    const float* pk = g_phik + tok0*PHI;
    for (int i = tid; i < CK*PHI; i += 256) sPhi[(i>>7)*PLD + (i&127)] = pk[i];
    const float* vr = v + tok0*DN;
    for (int i = tid; i < CK*DN;  i += 256) sV[(i>>6)*VLD + (i&63)]   = vr[i];
    __syncthreads();

    const int f0 = (tid >> 4) * 8, d0 = (tid & 15) * 4;
    u64p acc[8][2];
    #pragma unroll
    for (int i = 0; i < 8; i++) { acc[i][0] = 0ull; acc[i][1] = 0ull; }

    for (int n = 0; n < CK; n++) {
        float4 a0 = *(const float4*)&sPhi[n*PLD + f0];
        float4 a1 = *(const float4*)&sPhi[n*PLD + f0 + 4];
        float4 vv = *(const float4*)&sV[n*VLD + d0];
        const u64p vl = pk2(vv.x, vv.y), vh = pk2(vv.z, vv.w);
        u64p aa;
        aa = pk2(a0.x, a0.x); fma2(acc[0][0], aa, vl); fma2(acc[0][1], aa, vh);
        aa = pk2(a0.y, a0.y); fma2(acc[1][0], aa, vl); fma2(acc[1][1], aa, vh);
        aa = pk2(a0.z, a0.z); fma2(acc[2][0], aa, vl); fma2(acc[2][1], aa, vh);
        aa = pk2(a0.w, a0.w); fma2(acc[3][0], aa, vl); fma2(acc[3][1], aa, vh);
        aa = pk2(a1.x, a1.x); fma2(acc[4][0], aa, vl); fma2(acc[4][1], aa, vh);
        aa = pk2(a1.y, a1.y); fma2(acc[5][0], aa, vl); fma2(acc[5][1], aa, vh);
        aa = pk2(a1.z, a1.z); fma2(acc[6][0], aa, vl); fma2(acc[6][1], aa, vh);
        aa = pk2(a1.w, a1.w); fma2(acc[7][0], aa, vl); fma2(acc[7][1], aa, vh);
    }

    float* So = g_state + ((size_t)bh*NC + c)*(PHI*DN);
    #pragma unroll
    for (int i = 0; i < 8; i++) {
        float2 p0 = upk(acc[i][0]), p1 = upk(acc[i][1]);
        So[(f0+i)*DN + d0 + 0] = p0.x;
        So[(f0+i)*DN + d0 + 1] = p0.y;
        So[(f0+i)*DN + d0 + 2] = p1.x;
        So[(f0+i)*DN + d0 + 3] = p1.y;
    }

    if (tid < PHI) {
        float z = 0.f;
        for (int n = 0; n < CK; n++) z += sPhi[n*PLD + tid];
        g_zst[((size_t)bh*NC + c)*PHI + tid] = z;
    }
}

// ============================================================================
// Pass 2b: exclusive prefix over chunks — fully parallel register scans.
// ============================================================================
__global__ __launch_bounds__(256) void prefix_kernel()
{
    const int t = blockIdx.x * 256 + threadIdx.x;
    if (blockIdx.y == 0) {
        const int bh = t >> 13, idx = t & 8191;
        const size_t base = ((size_t)bh*NC)*(PHI*DN) + idx;
        float vals[NC];
        #pragma unroll
        for (int c = 0; c < NC; c++) vals[c] = g_state[base + (size_t)c*(PHI*DN)];
        float run = 0.f;
        #pragma unroll
        for (int c = 0; c < NC; c++) {
            g_spref[base + (size_t)c*(PHI*DN)] = run;
            run += vals[c];
        }
    } else {
        if (t >= BH*PHI) return;
        const int bh = t >> 7, idx = t & 127;
        const size_t base = ((size_t)bh*NC)*PHI + idx;
        float vals[NC];
        #pragma unroll
        for (int c = 0; c < NC; c++) vals[c] = g_zst[base + (size_t)c*PHI];
        float run = 0.f;
        #pragma unroll
        for (int c = 0; c < NC; c++) {
            g_zpref[base + (size_t)c*PHI] = run;
            run += vals[c];
        }
    }
}

// ============================================================================
// Pass 3: per-chunk output. 512 threads, f32x2 FMA, causal work-skipping.
//   Phase C rows per warp: m_i = w + 16*i  ->  jmax(i) = i>>1 (compile-time,
//   identical for every warp -> balanced). 37.5% of score FMAs skipped.
//   Phase E: thread rows 4*tyo..4*tyo+3 -> loop n only to 4*(tyo+1).
// ============================================================================
__global__ __launch_bounds__(512) void out_kernel(
    const float* __restrict__ v, float* __restrict__ out)
{
    extern __shared__ float sm[];
    float* sQ   = sm;                    // 128*PLD              (phi_q)
    float* sSp  = sQ  + CK*PLD;          // 128*VLD   S_pref, then V
    float* sKS  = sSp + PHI*VLD;         // 128*PLD   phi_k, then scores
    float* sZ   = sKS + CK*PLD;          // 128
    float* sDen = sZ  + PHI;             // 128

    const int c = blockIdx.x, bh = blockIdx.y, tid = threadIdx.x;
    const size_t tok0 = (size_t)bh*LN + (size_t)c*CK;

    // ---- load Q [128,128], S_pref [128,64], z_pref ----
    {
        const float4* pq = (const float4*)(g_phiq + tok0*PHI);
        for (int i = tid; i < CK*PHI/4; i += 512) {
            const int r = i >> 5, c4 = i & 31;
            *(float4*)&sQ[r*PLD + c4*4] = pq[i];
        }
        const float4* sp = (const float4*)(g_spref + ((size_t)bh*NC + c)*(PHI*DN));
        for (int i = tid; i < PHI*DN/4; i += 512) {
            const int r = i >> 4, c4 = i & 15;
            *(float4*)&sSp[r*VLD + c4*4] = sp[i];
        }
        if (tid < PHI) sZ[tid] = g_zpref[((size_t)bh*NC + c)*PHI + tid];
    }
    __syncthreads();

    // ---- Phase A: inter-chunk denominator (packed dot) ----
    if (tid < CK) {
        u64p ds2 = 0ull;
        #pragma unroll 8
        for (int f = 0; f < PHI; f += 4) {
            float4 q4 = *(const float4*)&sQ[tid*PLD + f];
            float4 z4 = *(const float4*)&sZ[f];
            fma2(ds2, pk2(q4.x, q4.y), pk2(z4.x, z4.y));
            fma2(ds2, pk2(q4.z, q4.w), pk2(z4.z, z4.w));
        }
        float2 dp = upk(ds2);
        sDen[tid] = dp.x + dp.y;
    }

    const int tyo = tid >> 4, txo = tid & 15;   // 32 x 16
    const int m0o = tyo * 4, d0 = txo * 4;
    u64p y2[4][2];
    #pragma unroll
    for (int i = 0; i < 4; i++) { y2[i][0] = 0ull; y2[i][1] = 0ull; }

    // ---- Phase A2: y = phiQ @ S_pref (packed broadcast form) ----
    for (int f = 0; f < PHI; f += 4) {
        float4 sp0 = *(const float4*)&sSp[(f+0)*VLD + d0];
        float4 sp1 = *(const float4*)&sSp[(f+1)*VLD + d0];
        float4 sp2 = *(const float4*)&sSp[(f+2)*VLD + d0];
        float4 sp3 = *(const float4*)&sSp[(f+3)*VLD + d0];
        const u64p p0l = pk2(sp0.x,sp0.y), p0h = pk2(sp0.z,sp0.w);
        const u64p p1l = pk2(sp1.x,sp1.y), p1h = pk2(sp1.z,sp1.w);
        const u64p p2l = pk2(sp2.x,sp2.y), p2h = pk2(sp2.z,sp2.w);
        const u64p p3l = pk2(sp3.x,sp3.y), p3h = pk2(sp3.z,sp3.w);
        #pragma unroll
        for (int i = 0; i < 4; i++) {
            float4 q4 = *(const float4*)&sQ[(m0o+i)*PLD + f];
            u64p aa;
            aa = pk2(q4.x, q4.x); fma2(y2[i][0], aa, p0l); fma2(y2[i][1], aa, p0h);
            aa = pk2(q4.y, q4.y); fma2(y2[i][0], aa, p1l); fma2(y2[i][1], aa, p1h);
            aa = pk2(q4.z, q4.z); fma2(y2[i][0], aa, p2l); fma2(y2[i][1], aa, p2h);
            aa = pk2(q4.w, q4.w); fma2(y2[i][0], aa, p3l); fma2(y2[i][1], aa, p3h);
        }
    }
    __syncthreads();   // done reading sSp -> V may overwrite

    // ---- Phase B: load K [128,128] and V [128,64] (V aliases sSp) ----
    {
        const float4* pk = (const float4*)(g_phik + tok0*PHI);
        for (int i = tid; i < CK*PHI/4; i += 512) {
            const int r = i >> 5, c4 = i & 31;
            *(float4*)&sKS[r*PLD + c4*4] = pk[i];
        }
        const float4* vr = (const float4*)(v + tok0*DN);
        for (int i = tid; i < CK*DN/4; i += 512) {
            const int r = i >> 4, c4 = i & 15;
            *(float4*)&sSp[r*VLD + c4*4] = vr[i];
        }
    }
    __syncthreads();

    // ---- Phase C: scores with causal skipping. warp w owns rows
    //      m_i = w + 16*i (i=0..7); lane covers n = lane + 32*j.
    //      Row m_i only needs j <= jmax = i>>1 (compile-time, warp-uniform).
    const int w    = tid >> 5;
    const int lane = tid & 31;

    u64p s2[8][4];   // only [i][j] with j <= i>>1 are live
    #pragma unroll
    for (int i = 0; i < 8; i++)
        #pragma unroll
        for (int j = 0; j < 4; j++)
            if (j <= (i >> 1)) s2[i][j] = 0ull;

    for (int f = 0; f < PHI; f += 4) {
        float4 k0 = *(const float4*)&sKS[(lane      )*PLD + f];
        float4 k1 = *(const float4*)&sKS[(lane + 32 )*PLD + f];
        float4 k2 = *(const float4*)&sKS[(lane + 64 )*PLD + f];
        float4 k3 = *(const float4*)&sKS[(lane + 96 )*PLD + f];
        u64p kl[4], kh[4];
        kl[0] = pk2(k0.x,k0.y); kh[0] = pk2(k0.z,k0.w);
        kl[1] = pk2(k1.x,k1.y); kh[1] = pk2(k1.z,k1.w);
        kl[2] = pk2(k2.x,k2.y); kh[2] = pk2(k2.z,k2.w);
        kl[3] = pk2(k3.x,k3.y); kh[3] = pk2(k3.z,k3.w);
        #pragma unroll
        for (int i = 0; i < 8; i++) {
            float4 q4 = *(const float4*)&sQ[(w + 16*i)*PLD + f];
            const u64p ql = pk2(q4.x,q4.y), qh = pk2(q4.z,q4.w);
            #pragma unroll
            for (int j = 0; j < 4; j++) {
                if (j <= (i >> 1)) {
                    fma2(s2[i][j], ql, kl[j]);
                    fma2(s2[i][j], qh, kh[j]);
                }
            }
        }
    }

    // horizontal sum, causal mask, per-row warp reduction into sDen
    float s[8][4];
    #pragma unroll
    for (int i = 0; i < 8; i++) {
        const int m = w + 16*i;
        const int jm = i >> 1;
        float ds = 0.f;
        #pragma unroll
        for (int j = 0; j < 4; j++) {
            float sv_;
            if (j < jm) {                      // fully below diagonal
                float2 p = upk(s2[i][j]);
                sv_ = p.x + p.y;
            } else if (j == jm) {              // boundary group: elementwise mask
                float2 p = upk(s2[i][j]);
                sv_ = (lane + 32*j <= m) ? (p.x + p.y) : 0.f;
            } else {                           // fully masked: known zero
                sv_ = 0.f;
            }
            s[i][j] = sv_;
            ds += sv_;
        }
        #pragma unroll
        for (int off = 16; off; off >>= 1)
            ds += __shfl_xor_sync(0xffffffffu, ds, off);
        if (lane == 0) sDen[m] += ds;   // rows partition across warps
    }
    __syncthreads();   // all K reads done -> scores may overwrite sKS

    // ---- Phase D: stage masked scores over K smem ----
    #pragma unroll
    for (int i = 0; i < 8; i++) {
        #pragma unroll
        for (int j = 0; j < 4; j++)
            sKS[(w + 16*i)*PLD + lane + 32*j] = s[i][j];
    }
    __syncthreads();

    // ---- Phase E: y += S @ V (packed broadcast), causal early exit ----
    // rows 4*tyo..4*tyo+3 need only n <= 4*tyo+3; staged zeros beyond are exact.
    const int nsteps = tyo + 1;
    for (int t = 0; t < nsteps; t++) {
        const int n = t * 4;
        float4 v0 = *(const float4*)&sSp[(n+0)*VLD + d0];
        float4 v1 = *(const float4*)&sSp[(n+1)*VLD + d0];
        float4 v2 = *(const float4*)&sSp[(n+2)*VLD + d0];
        float4 v3 = *(const float4*)&sSp[(n+3)*VLD + d0];
        const u64p v0l = pk2(v0.x,v0.y), v0h = pk2(v0.z,v0.w);
        const u64p v1l = pk2(v1.x,v1.y), v1h = pk2(v1.z,v1.w);
        const u64p v2l = pk2(v2.x,v2.y), v2h = pk2(v2.z,v2.w);
        const u64p v3l = pk2(v3.x,v3.y), v3h = pk2(v3.z,v3.w);
        #pragma unroll
        for (int i = 0; i < 4; i++) {
            float4 s4 = *(const float4*)&sKS[(m0o+i)*PLD + n];
            u64p aa;
            aa = pk2(s4.x, s4.x); fma2(y2[i][0], aa, v0l); fma2(y2[i][1], aa, v0h);
            aa = pk2(s4.y, s4.y); fma2(y2[i][0], aa, v1l); fma2(y2[i][1], aa, v1h);
            aa = pk2(s4.z, s4.z); fma2(y2[i][0], aa, v2l); fma2(y2[i][1], aa, v2h);
            aa = pk2(s4.w, s4.w); fma2(y2[i][0], aa, v3l); fma2(y2[i][1], aa, v3h);
        }
    }

    float* orow = out + tok0*DN;
    #pragma unroll
    for (int i = 0; i < 4; i++) {
        const float inv = 1.f / (sDen[m0o+i] + EPSF);
        float2 p0 = upk(y2[i][0]), p1 = upk(y2[i][1]);
        orow[(size_t)(m0o+i)*DN + d0 + 0] = p0.x * inv;
        orow[(size_t)(m0o+i)*DN + d0 + 1] = p0.y * inv;
        orow[(size_t)(m0o+i)*DN + d0 + 2] = p1.x * inv;
        orow[(size_t)(m0o+i)*DN + d0 + 3] = p1.y * inv;
    }
}

// ============================================================================
extern "C" void kernel_launch(void* const* d_in, const int* in_sizes, int n_in,
                              void* d_out, int out_size)
{
    const float* q  = (const float*)d_in[0];
    const float* k  = (const float*)d_in[1];
    const float* v  = (const float*)d_in[2];
    const float* Wq = (const float*)d_in[3];
    const float* Wk = (const float*)d_in[4];
    const int*   li = (const int*)d_in[5];
    float* out = (float*)d_out;

    const int SMEM_STATE = (CK*PLD + CK*VLD) * 4;                       // 102400 B
    const int SMEM_OUT   = (CK*PLD + PHI*VLD + CK*PLD + PHI + CK) * 4;  // 171008 B
    cudaFuncSetAttribute(state_kernel, cudaFuncAttributeMaxDynamicSharedMemorySize, SMEM_STATE);
    cudaFuncSetAttribute(out_kernel,   cudaFuncAttributeMaxDynamicSharedMemorySize, SMEM_OUT);

    dim3 g1(LN/32, BH, 2);
    fmap_kernel<<<g1, 256>>>(q, k, Wq, Wk, li);

    dim3 g2(NC, BH);
    state_kernel<<<g2, 256, SMEM_STATE>>>(v);
    prefix_kernel<<<dim3(1024, 2), 256>>>();
    out_kernel<<<g2, 512, SMEM_OUT>>>(v, out);
}

// round 10
// speedup vs baseline: 2.1276x; 1.0701x over previous
#include <cuda_runtime.h>

// ---------------- problem constants (from reference setup_inputs) ----------
#define BN   2
#define HN   16
#define BH   32          // B*H
#define LN   2048
#define DN   64
#define FN   64
#define PHI  128         // 2F
#define CK   128         // chunk length
#define NC   16          // LN/CK
#define EPSF 1e-12f

#define PLD  132         // padded leading dim for [*, 128] tiles
#define VLD  68          // padded leading dim for [*, 64] tiles

typedef unsigned long long u64p;   // packed float2 in one 64-bit reg

__device__ __forceinline__ u64p pk2(float a, float b) {
    u64p r; asm("mov.b64 %0, {%1, %2};" : "=l"(r) : "f"(a), "f"(b)); return r;
}
__device__ __forceinline__ void fma2(u64p& d, u64p a, u64p b) {
    asm("fma.rn.f32x2 %0, %1, %2, %0;" : "+l"(d) : "l"(a), "l"(b));
}
__device__ __forceinline__ float2 upk(u64p p) {
    float2 v; asm("mov.b64 {%0, %1}, %2;" : "=f"(v.x), "=f"(v.y) : "l"(p)); return v;
}

// ---------------- scratch (static device globals; no allocation) -----------
__device__ float g_phiq[(size_t)BH*LN*PHI];      // 33.5 MB
__device__ float g_phik[(size_t)BH*LN*PHI];      // 33.5 MB
__device__ float g_state[(size_t)BH*NC*PHI*DN];  // 16.8 MB  per-chunk K^T V
__device__ float g_zst  [(size_t)BH*NC*PHI];
__device__ float g_spref[(size_t)BH*NC*PHI*DN];
__device__ float g_zpref[(size_t)BH*NC*PHI];

// ============================================================================
// Pass 1: hedgehog feature map.  phi = clip([softmax(xW), softmax(-xW)], eps)
// grid (LN/32, BH, 2), block 256 (8 warps). Each warp handles 4 rows.
// ============================================================================
__global__ __launch_bounds__(256) void fmap_kernel(
    const float* __restrict__ q, const float* __restrict__ k,
    const float* __restrict__ Wq, const float* __restrict__ Wk,
    const int* __restrict__ lidx)
{
    __shared__ float sW[DN*FN];      // 16 KB
    __shared__ float sx[32][68];

    const int which = blockIdx.z;
    const float* x = which ? k  : q;
    const float* W = which ? Wk : Wq;

    const int bh  = blockIdx.y;
    const int h   = bh % HN;
    const int tid = threadIdx.x;
    const int li  = lidx[0];

    const float* Wh = W + ((size_t)li*HN + h)*DN*FN;
    for (int i = tid; i < DN*FN/4; i += 256)
        ((float4*)sW)[i] = ((const float4*)Wh)[i];

    const int row0 = blockIdx.x * 32;
    const float* xr = x + ((size_t)bh*LN + row0)*DN;
    for (int i = tid; i < 32*DN/4; i += 256) {
        const int r = i >> 4, c = i & 15;
        *(float4*)&sx[r][c*4] = ((const float4*)xr)[i];
    }
    __syncthreads();

    const int w    = tid >> 5;
    const int lane = tid & 31;

    float o[4][2];
    #pragma unroll
    for (int r = 0; r < 4; r++) { o[r][0] = 0.f; o[r][1] = 0.f; }

    #pragma unroll 4
    for (int d = 0; d < DN; d++) {
        const float w0 = sW[d*FN + lane];
        const float w1 = sW[d*FN + lane + 32];
        #pragma unroll
        for (int r = 0; r < 4; r++) {
            const float xv = sx[w*4 + r][d];
            o[r][0] += xv * w0;
            o[r][1] += xv * w1;
        }
    }

    float* phidst = which ? g_phik : g_phiq;
    #pragma unroll
    for (int r = 0; r < 4; r++) {
        float o0 = o[r][0], o1 = o[r][1];
        float mx = fmaxf(o0, o1), mn = fminf(o0, o1);
        #pragma unroll
        for (int off = 16; off; off >>= 1) {
            mx = fmaxf(mx, __shfl_xor_sync(0xffffffffu, mx, off));
            mn = fminf(mn, __shfl_xor_sync(0xffffffffu, mn, off));
        }
        float e0 = __expf(o0 - mx), e1 = __expf(o1 - mx);   // softmax(o)
        float n0 = __expf(mn - o0), n1 = __expf(mn - o1);   // softmax(-o)
        float se = e0 + e1, sn = n0 + n1;
        #pragma unroll
        for (int off = 16; off; off >>= 1) {
            se += __shfl_xor_sync(0xffffffffu, se, off);
            sn += __shfl_xor_sync(0xffffffffu, sn, off);
        }
        const float ie = 1.f/se, in_ = 1.f/sn;
        float* pr = phidst + ((size_t)bh*LN + row0 + w*4 + r)*PHI;
        pr[lane]      = fmaxf(e0*ie,  EPSF);
        pr[lane + 32] = fmaxf(e1*ie,  EPSF);
        pr[64 + lane] = fmaxf(n0*in_, EPSF);
        pr[96 + lane] = fmaxf(n1*in_, EPSF);
    }
}

// ============================================================================
// Pass 2: per-chunk states  S_c[f][d] = sum_n phi_k[n][f] v[n][d],  z_c[f]
// grid (NC, BH), block 256, dynamic smem 100 KB. Packed f32x2 accumulators.
// ============================================================================
__global__ __launch_bounds__(256) void state_kernel(const float* __restrict__ v)
{
    extern __shared__ float sm[];
    float* sPhi = sm;               // CK*PLD
    float* sV   = sm + CK*PLD;      // CK*VLD
    const int c = blockIdx.x, bh = blockIdx.y, tid = threadIdx.x;
    const size_t tok0 = (size_t)bh*LN + (size_t)c*CK;

    const float* pk = g_phik + tok0*PHI;
    for (int i = tid; i < CK*PHI; i += 256) sPhi[(i>>7)*PLD + (i&127)] = pk[i];
    const float* vr = v + tok0*DN;
    for (int i = tid; i < CK*DN;  i += 256) sV[(i>>6)*VLD + (i&63)]   = vr[i];
    __syncthreads();

    const int f0 = (tid >> 4) * 8, d0 = (tid & 15) * 4;
    u64p acc[8][2];
    #pragma unroll
    for (int i = 0; i < 8; i++) { acc[i][0] = 0ull; acc[i][1] = 0ull; }

    for (int n = 0; n < CK; n++) {
        float4 a0 = *(const float4*)&sPhi[n*PLD + f0];
        float4 a1 = *(const float4*)&sPhi[n*PLD + f0 + 4];
        float4 vv = *(const float4*)&sV[n*VLD + d0];
        const u64p vl = pk2(vv.x, vv.y), vh = pk2(vv.z, vv.w);
        u64p aa;
        aa = pk2(a0.x, a0.x); fma2(acc[0][0], aa, vl); fma2(acc[0][1], aa, vh);
        aa = pk2(a0.y, a0.y); fma2(acc[1][0], aa, vl); fma2(acc[1][1], aa, vh);
        aa = pk2(a0.z, a0.z); fma2(acc[2][0], aa, vl); fma2(acc[2][1], aa, vh);
        aa = pk2(a0.w, a0.w); fma2(acc[3][0], aa, vl); fma2(acc[3][1], aa, vh);
        aa = pk2(a1.x, a1.x); fma2(acc[4][0], aa, vl); fma2(acc[4][1], aa, vh);
        aa = pk2(a1.y, a1.y); fma2(acc[5][0], aa, vl); fma2(acc[5][1], aa, vh);
        aa = pk2(a1.z, a1.z); fma2(acc[6][0], aa, vl); fma2(acc[6][1], aa, vh);
        aa = pk2(a1.w, a1.w); fma2(acc[7][0], aa, vl); fma2(acc[7][1], aa, vh);
    }

    float* So = g_state + ((size_t)bh*NC + c)*(PHI*DN);
    #pragma unroll
    for (int i = 0; i < 8; i++) {
        float2 p0 = upk(acc[i][0]), p1 = upk(acc[i][1]);
        So[(f0+i)*DN + d0 + 0] = p0.x;
        So[(f0+i)*DN + d0 + 1] = p0.y;
        So[(f0+i)*DN + d0 + 2] = p1.x;
        So[(f0+i)*DN + d0 + 3] = p1.y;
    }

    if (tid < PHI) {
        float z = 0.f;
        for (int n = 0; n < CK; n++) z += sPhi[n*PLD + tid];
        g_zst[((size_t)bh*NC + c)*PHI + tid] = z;
    }
}

// ============================================================================
// Pass 2b: exclusive prefix over chunks — fully parallel register scans.
// ============================================================================
__global__ __launch_bounds__(256) void prefix_kernel()
{
    const int t = blockIdx.x * 256 + threadIdx.x;
    if (blockIdx.y == 0) {
        const int bh = t >> 13, idx = t & 8191;
        const size_t base = ((size_t)bh*NC)*(PHI*DN) + idx;
        float vals[NC];
        #pragma unroll
        for (int c = 0; c < NC; c++) vals[c] = g_state[base + (size_t)c*(PHI*DN)];
        float run = 0.f;
        #pragma unroll
        for (int c = 0; c < NC; c++) {
            g_spref[base + (size_t)c*(PHI*DN)] = run;
            run += vals[c];
        }
    } else {
        if (t >= BH*PHI) return;
        const int bh = t >> 7, idx = t & 127;
        const size_t base = ((size_t)bh*NC)*PHI + idx;
        float vals[NC];
        #pragma unroll
        for (int c = 0; c < NC; c++) vals[c] = g_zst[base + (size_t)c*PHI];
        float run = 0.f;
        #pragma unroll
        for (int c = 0; c < NC; c++) {
            g_zpref[base + (size_t)c*PHI] = run;
            run += vals[c];
        }
    }
}

// ============================================================================
// Pass 3: per-chunk output. 512 threads, f32x2 FMA, causal skipping,
// de-serialized: all global loads upfront, 3 barriers total, no aliasing.
//   order: loads | bar | A(den), C(scores) | bar | D(stage)+denAdd, A2 | bar | E
// smem: 2*128*PLD + 2*128*VLD + 256 floats = 205,824 B (1 CTA/SM)
// ============================================================================
__global__ __launch_bounds__(512) void out_kernel(
    const float* __restrict__ v, float* __restrict__ out)
{
    extern __shared__ float sm[];
    float* sQ   = sm;                    // 128*PLD   phi_q
    float* sKS  = sQ  + CK*PLD;          // 128*PLD   phi_k, then scores
    float* sSp  = sKS + CK*PLD;          // 128*VLD   S_pref
    float* sV   = sSp + PHI*VLD;         // 128*VLD   V
    float* sZ   = sV  + CK*VLD;          // 128
    float* sDen = sZ  + PHI;             // 128

    const int c = blockIdx.x, bh = blockIdx.y, tid = threadIdx.x;
    const size_t tok0 = (size_t)bh*LN + (size_t)c*CK;

    // ---- ALL global loads upfront: Q, K, S_pref, V, z_pref ----
    {
        const float4* pq = (const float4*)(g_phiq + tok0*PHI);
        const float4* pk = (const float4*)(g_phik + tok0*PHI);
        for (int i = tid; i < CK*PHI/4; i += 512) {
            const int r = i >> 5, c4 = i & 31;
            *(float4*)&sQ [r*PLD + c4*4] = pq[i];
            *(float4*)&sKS[r*PLD + c4*4] = pk[i];
        }
        const float4* sp = (const float4*)(g_spref + ((size_t)bh*NC + c)*(PHI*DN));
        const float4* vr = (const float4*)(v + tok0*DN);
        for (int i = tid; i < PHI*DN/4; i += 512) {
            const int r = i >> 4, c4 = i & 15;
            *(float4*)&sSp[r*VLD + c4*4] = sp[i];
            *(float4*)&sV [r*VLD + c4*4] = vr[i];
        }
        if (tid < PHI) sZ[tid] = g_zpref[((size_t)bh*NC + c)*PHI + tid];
    }
    __syncthreads();   // ---- barrier 1 ----

    // ---- Phase A: inter-chunk denominator (packed dot) ----
    if (tid < CK) {
        u64p ds2 = 0ull;
        #pragma unroll 8
        for (int f = 0; f < PHI; f += 4) {
            float4 q4 = *(const float4*)&sQ[tid*PLD + f];
            float4 z4 = *(const float4*)&sZ[f];
            fma2(ds2, pk2(q4.x, q4.y), pk2(z4.x, z4.y));
            fma2(ds2, pk2(q4.z, q4.w), pk2(z4.z, z4.w));
        }
        float2 dp = upk(ds2);
        sDen[tid] = dp.x + dp.y;
    }

    // ---- Phase C: scores with causal skipping. warp w owns rows
    //      m_i = w + 16*i (i=0..7); lane covers n = lane + 32*j.
    //      Row m_i only needs j <= jmax = i>>1 (compile-time, warp-uniform).
    const int w    = tid >> 5;
    const int lane = tid & 31;

    u64p s2[8][4];   // only [i][j] with j <= i>>1 are live
    #pragma unroll
    for (int i = 0; i < 8; i++)
        #pragma unroll
        for (int j = 0; j < 4; j++)
            if (j <= (i >> 1)) s2[i][j] = 0ull;

    for (int f = 0; f < PHI; f += 4) {
        float4 k0 = *(const float4*)&sKS[(lane      )*PLD + f];
        float4 k1 = *(const float4*)&sKS[(lane + 32 )*PLD + f];
        float4 k2 = *(const float4*)&sKS[(lane + 64 )*PLD + f];
        float4 k3 = *(const float4*)&sKS[(lane + 96 )*PLD + f];
        u64p kl[4], kh[4];
        kl[0] = pk2(k0.x,k0.y); kh[0] = pk2(k0.z,k0.w);
        kl[1] = pk2(k1.x,k1.y); kh[1] = pk2(k1.z,k1.w);
        kl[2] = pk2(k2.x,k2.y); kh[2] = pk2(k2.z,k2.w);
        kl[3] = pk2(k3.x,k3.y); kh[3] = pk2(k3.z,k3.w);
        #pragma unroll
        for (int i = 0; i < 8; i++) {
            float4 q4 = *(const float4*)&sQ[(w + 16*i)*PLD + f];
            const u64p ql = pk2(q4.x,q4.y), qh = pk2(q4.z,q4.w);
            #pragma unroll
            for (int j = 0; j < 4; j++) {
                if (j <= (i >> 1)) {
                    fma2(s2[i][j], ql, kl[j]);
                    fma2(s2[i][j], qh, kh[j]);
                }
            }
        }
    }

    // horizontal sum + causal mask + warp-reduced row sums (kept in regs
    // across the barrier; sDen updated in the D region to avoid racing A).
    float s[8][4];
    float dsum[8];
    #pragma unroll
    for (int i = 0; i < 8; i++) {
        const int m = w + 16*i;
        const int jm = i >> 1;
        float ds = 0.f;
        #pragma unroll
        for (int j = 0; j < 4; j++) {
            float sv_;
            if (j < jm) {
                float2 p = upk(s2[i][j]);
                sv_ = p.x + p.y;
            } else if (j == jm) {
                float2 p = upk(s2[i][j]);
                sv_ = (lane + 32*j <= m) ? (p.x + p.y) : 0.f;
            } else {
                sv_ = 0.f;
            }
            s[i][j] = sv_;
            ds += sv_;
        }
        #pragma unroll
        for (int off = 16; off; off >>= 1)
            ds += __shfl_xor_sync(0xffffffffu, ds, off);
        dsum[i] = ds;
    }
    __syncthreads();   // ---- barrier 2: K reads done; A's sDen writes done ----

    // ---- Phase D: stage masked scores over K smem + fold row sums ----
    #pragma unroll
    for (int i = 0; i < 8; i++) {
        #pragma unroll
        for (int j = 0; j < 4; j++)
            sKS[(w + 16*i)*PLD + lane + 32*j] = s[i][j];
    }
    if (lane == 0) {
        #pragma unroll
        for (int i = 0; i < 8; i++)
            sDen[w + 16*i] += dsum[i];   // rows partition across warps
    }

    // ---- Phase A2: y = phiQ @ S_pref (packed broadcast form) ----
    const int tyo = tid >> 4, txo = tid & 15;   // 32 x 16
    const int m0o = tyo * 4, d0 = txo * 4;
    u64p y2[4][2];
    #pragma unroll
    for (int i = 0; i < 4; i++) { y2[i][0] = 0ull; y2[i][1] = 0ull; }

    for (int f = 0; f < PHI; f += 4) {
        float4 sp0 = *(const float4*)&sSp[(f+0)*VLD + d0];
        float4 sp1 = *(const float4*)&sSp[(f+1)*VLD + d0];
        float4 sp2 = *(const float4*)&sSp[(f+2)*VLD + d0];
        float4 sp3 = *(const float4*)&sSp[(f+3)*VLD + d0];
        const u64p p0l = pk2(sp0.x,sp0.y), p0h = pk2(sp0.z,sp0.w);
        const u64p p1l = pk2(sp1.x,sp1.y), p1h = pk2(sp1.z,sp1.w);
        const u64p p2l = pk2(sp2.x,sp2.y), p2h = pk2(sp2.z,sp2.w);
        const u64p p3l = pk2(sp3.x,sp3.y), p3h = pk2(sp3.z,sp3.w);
        #pragma unroll
        for (int i = 0; i < 4; i++) {
            float4 q4 = *(const float4*)&sQ[(m0o+i)*PLD + f];
            u64p aa;
            aa = pk2(q4.x, q4.x); fma2(y2[i][0], aa, p0l); fma2(y2[i][1], aa, p0h);
            aa = pk2(q4.y, q4.y); fma2(y2[i][0], aa, p1l); fma2(y2[i][1], aa, p1h);
            aa = pk2(q4.z, q4.z); fma2(y2[i][0], aa, p2l); fma2(y2[i][1], aa, p2h);
            aa = pk2(q4.w, q4.w); fma2(y2[i][0], aa, p3l); fma2(y2[i][1], aa, p3h);
        }
    }
    __syncthreads();   // ---- barrier 3: scores staged + sDen complete ----

    // ---- Phase E: y += S @ V (packed broadcast), causal early exit ----
    const int nsteps = tyo + 1;
    for (int t = 0; t < nsteps; t++) {
        const int n = t * 4;
        float4 v0 = *(const float4*)&sV[(n+0)*VLD + d0];
        float4 v1 = *(const float4*)&sV[(n+1)*VLD + d0];
        float4 v2 = *(const float4*)&sV[(n+2)*VLD + d0];
        float4 v3 = *(const float4*)&sV[(n+3)*VLD + d0];
        const u64p v0l = pk2(v0.x,v0.y), v0h = pk2(v0.z,v0.w);
        const u64p v1l = pk2(v1.x,v1.y), v1h = pk2(v1.z,v1.w);
        const u64p v2l = pk2(v2.x,v2.y), v2h = pk2(v2.z,v2.w);
        const u64p v3l = pk2(v3.x,v3.y), v3h = pk2(v3.z,v3.w);
        #pragma unroll
        for (int i = 0; i < 4; i++) {
            float4 s4 = *(const float4*)&sKS[(m0o+i)*PLD + n];
            u64p aa;
            aa = pk2(s4.x, s4.x); fma2(y2[i][0], aa, v0l); fma2(y2[i][1], aa, v0h);
            aa = pk2(s4.y, s4.y); fma2(y2[i][0], aa, v1l); fma2(y2[i][1], aa, v1h);
            aa = pk2(s4.z, s4.z); fma2(y2[i][0], aa, v2l); fma2(y2[i][1], aa, v2h);
            aa = pk2(s4.w, s4.w); fma2(y2[i][0], aa, v3l); fma2(y2[i][1], aa, v3h);
        }
    }

    float* orow = out + tok0*DN;
    #pragma unroll
    for (int i = 0; i < 4; i++) {
        const float inv = 1.f / (sDen[m0o+i] + EPSF);
        float2 p0 = upk(y2[i][0]), p1 = upk(y2[i][1]);
        orow[(size_t)(m0o+i)*DN + d0 + 0] = p0.x * inv;
        orow[(size_t)(m0o+i)*DN + d0 + 1] = p0.y * inv;
        orow[(size_t)(m0o+i)*DN + d0 + 2] = p1.x * inv;
        orow[(size_t)(m0o+i)*DN + d0 + 3] = p1.y * inv;
    }
}

// ============================================================================
extern "C" void kernel_launch(void* const* d_in, const int* in_sizes, int n_in,
                              void* d_out, int out_size)
{
    const float* q  = (const float*)d_in[0];
    const float* k  = (const float*)d_in[1];
    const float* v  = (const float*)d_in[2];
    const float* Wq = (const float*)d_in[3];
    const float* Wk = (const float*)d_in[4];
    const int*   li = (const int*)d_in[5];
    float* out = (float*)d_out;

    const int SMEM_STATE = (CK*PLD + CK*VLD) * 4;                            // 102400 B
    const int SMEM_OUT   = (2*CK*PLD + PHI*VLD + CK*VLD + PHI + CK) * 4;     // 205824 B
    cudaFuncSetAttribute(state_kernel, cudaFuncAttributeMaxDynamicSharedMemorySize, SMEM_STATE);
    cudaFuncSetAttribute(out_kernel,   cudaFuncAttributeMaxDynamicSharedMemorySize, SMEM_OUT);

    dim3 g1(LN/32, BH, 2);
    fmap_kernel<<<g1, 256>>>(q, k, Wq, Wk, li);

    dim3 g2(NC, BH);
    state_kernel<<<g2, 256, SMEM_STATE>>>(v);
    prefix_kernel<<<dim3(1024, 2), 256>>>();
    out_kernel<<<g2, 512, SMEM_OUT>>>(v, out);
}